// round 1
// baseline (speedup 1.0000x reference)
#include <cuda_runtime.h>
#include <cuda_bf16.h>
#include <stdint.h>

// Problem constants
#define M_ROWS 8192
#define D_MODEL 768
#define N_LAT 16384
#define TOPK 32

// ---------------------------------------------------------------------------
// Scratch (device globals; no runtime allocation allowed)
// ---------------------------------------------------------------------------
__device__ float g_WdecT[(size_t)N_LAT * D_MODEL];   // 48 MB: W_dec transposed to [N_LAT, D_MODEL]
__device__ int   g_tk_idx[(size_t)M_ROWS * TOPK];
__device__ float g_tk_val[(size_t)M_ROWS * TOPK];

// ---------------------------------------------------------------------------
// Kernel 1: encoder GEMM  pre[M, N_LAT] = x[M, D] @ W_enc[N_LAT, D]^T + b_enc
// fp32 SIMT, 128x128 tile, BK=16, 256 threads, 8x8 per-thread microtile.
// ---------------------------------------------------------------------------
__global__ void __launch_bounds__(256) gemm_enc_kernel(
    const float* __restrict__ A,      // x [M, K]
    const float* __restrict__ B,      // W_enc [N, K]
    const float* __restrict__ bias,   // b_enc [N]
    float* __restrict__ C)            // pre [M, N]
{
    const int K = D_MODEL;
    const int N = N_LAT;
    __shared__ float As[16][128];
    __shared__ float Bs[16][128];

    const int bm  = blockIdx.y * 128;
    const int bn  = blockIdx.x * 128;
    const int tid = threadIdx.x;

    // global-load mapping: 2 threads per row, 8 contiguous k each
    const int lrow = tid >> 1;           // 0..127
    const int lk   = (tid & 1) * 8;      // 0 or 8
    const float* Ag = A + (size_t)(bm + lrow) * K + lk;
    const float* Bg = B + (size_t)(bn + lrow) * K + lk;

    const int tm = (tid >> 4) * 8;       // 0..120
    const int tn = (tid & 15) * 8;       // 0..120

    float acc[8][8];
    #pragma unroll
    for (int i = 0; i < 8; ++i)
        #pragma unroll
        for (int j = 0; j < 8; ++j)
            acc[i][j] = 0.0f;

    for (int kt = 0; kt < K; kt += 16) {
        float4 a0 = *(const float4*)(Ag + kt);
        float4 a1 = *(const float4*)(Ag + kt + 4);
        float4 b0 = *(const float4*)(Bg + kt);
        float4 b1 = *(const float4*)(Bg + kt + 4);
        __syncthreads();  // previous iteration's consumers done
        As[lk+0][lrow]=a0.x; As[lk+1][lrow]=a0.y; As[lk+2][lrow]=a0.z; As[lk+3][lrow]=a0.w;
        As[lk+4][lrow]=a1.x; As[lk+5][lrow]=a1.y; As[lk+6][lrow]=a1.z; As[lk+7][lrow]=a1.w;
        Bs[lk+0][lrow]=b0.x; Bs[lk+1][lrow]=b0.y; Bs[lk+2][lrow]=b0.z; Bs[lk+3][lrow]=b0.w;
        Bs[lk+4][lrow]=b1.x; Bs[lk+5][lrow]=b1.y; Bs[lk+6][lrow]=b1.z; Bs[lk+7][lrow]=b1.w;
        __syncthreads();
        #pragma unroll
        for (int kk = 0; kk < 16; ++kk) {
            float4 af0 = *(const float4*)&As[kk][tm];
            float4 af1 = *(const float4*)&As[kk][tm + 4];
            float4 bf0 = *(const float4*)&Bs[kk][tn];
            float4 bf1 = *(const float4*)&Bs[kk][tn + 4];
            float a[8] = {af0.x, af0.y, af0.z, af0.w, af1.x, af1.y, af1.z, af1.w};
            float b[8] = {bf0.x, bf0.y, bf0.z, bf0.w, bf1.x, bf1.y, bf1.z, bf1.w};
            #pragma unroll
            for (int i = 0; i < 8; ++i)
                #pragma unroll
                for (int j = 0; j < 8; ++j)
                    acc[i][j] = fmaf(a[i], b[j], acc[i][j]);
        }
    }

    float bv[8];
    #pragma unroll
    for (int j = 0; j < 8; ++j) bv[j] = bias[bn + tn + j];

    #pragma unroll
    for (int i = 0; i < 8; ++i) {
        float4 o0 = make_float4(acc[i][0]+bv[0], acc[i][1]+bv[1], acc[i][2]+bv[2], acc[i][3]+bv[3]);
        float4 o1 = make_float4(acc[i][4]+bv[4], acc[i][5]+bv[5], acc[i][6]+bv[6], acc[i][7]+bv[7]);
        float* cp = C + (size_t)(bm + tm + i) * N + bn + tn;
        *(float4*)cp       = o0;
        *(float4*)(cp + 4) = o1;
    }
}

// ---------------------------------------------------------------------------
// Kernel 2: W_dec [D_MODEL, N_LAT] -> g_WdecT [N_LAT, D_MODEL]
// ---------------------------------------------------------------------------
__global__ void transpose_kernel(const float* __restrict__ Wdec)
{
    __shared__ float tile[32][33];
    const int l  = blockIdx.x * 32 + threadIdx.x;  // latent dim (fast in Wdec)
    const int d0 = blockIdx.y * 32;
    #pragma unroll
    for (int j = threadIdx.y; j < 32; j += 8)
        tile[j][threadIdx.x] = Wdec[(size_t)(d0 + j) * N_LAT + l];
    __syncthreads();
    const int d  = d0 + threadIdx.x;
    const int l0 = blockIdx.x * 32;
    #pragma unroll
    for (int j = threadIdx.y; j < 32; j += 8)
        g_WdecT[(size_t)(l0 + j) * D_MODEL + d] = tile[threadIdx.x][j];
}

// ---------------------------------------------------------------------------
// Kernel 3: exact top-32 per row via 4-pass radix select on monotone float keys.
// One block (256 threads) per row; row cached in 64KB dynamic smem.
// Ties at the threshold taken in ascending index order (matches lax.top_k).
// ---------------------------------------------------------------------------
__global__ void topk_kernel(const float* __restrict__ pre, float* __restrict__ latents)
{
    extern __shared__ unsigned skeys[];        // 16384 keys
    __shared__ unsigned hist[256];
    __shared__ unsigned s_prefix, s_remk;

    const int row = blockIdx.x;
    const float* prow = pre + (size_t)row * N_LAT;
    const int tid = threadIdx.x;

    // Monotone map: larger float -> larger unsigned key
    for (int i = tid; i < N_LAT; i += 256) {
        unsigned u = __float_as_uint(prow[i]);
        skeys[i] = (u & 0x80000000u) ? ~u : (u | 0x80000000u);
    }
    __syncthreads();

    unsigned prefix = 0u, remk = TOPK;
    for (int shift = 24; shift >= 0; shift -= 8) {
        const unsigned mask_hi = (shift == 24) ? 0u : (0xFFFFFFFFu << (shift + 8));
        hist[tid] = 0u;
        __syncthreads();
        for (int i = tid; i < N_LAT; i += 256) {
            unsigned k = skeys[i];
            if ((k & mask_hi) == prefix)
                atomicAdd(&hist[(k >> shift) & 0xFFu], 1u);
        }
        __syncthreads();
        if (tid == 0) {
            unsigned cum = 0; int b = 255;
            for (; b > 0; --b) {
                if (cum + hist[b] >= remk) break;
                cum += hist[b];
            }
            s_prefix = prefix | ((unsigned)b << shift);
            s_remk   = remk - cum;
        }
        __syncthreads();
        prefix = s_prefix;
        remk   = s_remk;
        __syncthreads();
    }

    const unsigned T = prefix;  // exact threshold key; take all > T, plus remk ties == T

    // Warp 0 collects deterministically in index order.
    if (tid < 32) {
        unsigned taken = 0, need_eq = remk;
        const unsigned lmask = (1u << tid) - 1u;
        for (int base = 0; base < N_LAT && taken < TOPK; base += 32) {
            const unsigned k = skeys[base + tid];
            const bool gt = (k > T);
            const bool eq = (k == T);
            const unsigned bg = __ballot_sync(0xFFFFFFFFu, gt);
            const unsigned be = __ballot_sync(0xFFFFFFFFu, eq);
            const unsigned ng = __popc(bg);
            const unsigned ne = __popc(be);
            const unsigned take_eq = (ne < need_eq) ? ne : need_eq;
            int slot = -1;
            if (gt) {
                slot = (int)(taken + __popc(bg & lmask));
            } else if (eq) {
                const unsigned r = __popc(be & lmask);
                if (r < take_eq) slot = (int)(taken + ng + r);
            }
            if (slot >= 0) {
                const int idx = base + tid;
                const float v = fmaxf(prow[idx], 0.0f);  // relu
                g_tk_idx[(size_t)row * TOPK + slot] = idx;
                g_tk_val[(size_t)row * TOPK + slot] = v;
                latents[(size_t)row * N_LAT + idx] = v;
            }
            taken   += ng + take_eq;
            need_eq -= take_eq;
        }
    }
}

// ---------------------------------------------------------------------------
// Kernel 4: sparse decode  rec[row] = b_dec + sum_j val_j * WdecT[idx_j, :]
// ---------------------------------------------------------------------------
__global__ void __launch_bounds__(256) decode_kernel(
    const float* __restrict__ b_dec, float* __restrict__ rec)
{
    const int row = blockIdx.x;
    __shared__ int   sidx[TOPK];
    __shared__ float sval[TOPK];
    const int tid = threadIdx.x;
    if (tid < TOPK) {
        sidx[tid] = g_tk_idx[(size_t)row * TOPK + tid];
        sval[tid] = g_tk_val[(size_t)row * TOPK + tid];
    }
    __syncthreads();
    for (int d = tid; d < D_MODEL; d += 256) {
        float acc = b_dec[d];
        #pragma unroll
        for (int j = 0; j < TOPK; ++j)
            acc = fmaf(sval[j], g_WdecT[(size_t)sidx[j] * D_MODEL + d], acc);
        rec[(size_t)row * D_MODEL + d] = acc;
    }
}

// ---------------------------------------------------------------------------
// Launch: outputs concatenated as (latents, reconstructed, pre_activation)
// ---------------------------------------------------------------------------
extern "C" void kernel_launch(void* const* d_in, const int* in_sizes, int n_in,
                              void* d_out, int out_size)
{
    const float* x     = (const float*)d_in[0];
    const float* W_enc = (const float*)d_in[1];
    const float* b_enc = (const float*)d_in[2];
    const float* W_dec = (const float*)d_in[3];
    const float* b_dec = (const float*)d_in[4];

    float* out = (float*)d_out;
    const size_t LAT_ELEMS = (size_t)M_ROWS * N_LAT;
    const size_t REC_ELEMS = (size_t)M_ROWS * D_MODEL;
    float* latents = out;
    float* rec     = out + LAT_ELEMS;
    float* pre     = out + LAT_ELEMS + REC_ELEMS;

    cudaFuncSetAttribute(topk_kernel, cudaFuncAttributeMaxDynamicSharedMemorySize, 65536);

    // zero the latents region (poisoned to 0xAA by harness)
    cudaMemsetAsync(latents, 0, LAT_ELEMS * sizeof(float), 0);

    // encoder GEMM -> pre
    gemm_enc_kernel<<<dim3(N_LAT / 128, M_ROWS / 128), 256>>>(x, W_enc, b_enc, pre);

    // transpose W_dec (independent of GEMM)
    transpose_kernel<<<dim3(N_LAT / 32, D_MODEL / 32), dim3(32, 8)>>>(W_dec);

    // exact top-32 + scatter into latents + record (idx, val)
    topk_kernel<<<M_ROWS, 256, 65536>>>(pre, latents);

    // sparse decode
    decode_kernel<<<M_ROWS, 256>>>(b_dec, rec);
}

// round 4
// speedup vs baseline: 1.3020x; 1.3020x over previous
#include <cuda_runtime.h>
#include <cuda_bf16.h>
#include <stdint.h>

#define M_ROWS 8192
#define D_MODEL 768
#define N_LAT 16384
#define TOPK 32
#define NCAND 64

// GEMM tiling (mma.sync path)
#define BM 128
#define BN 128
#define BK 32
#define KCHUNKS (D_MODEL / BK)      // 24
#define ROWB 80                      // padded row stride in bytes (40 bf16)
#define TILE_B (128 * ROWB)          // 10240 bytes per operand tile
#define ST_A0 0
#define ST_A1 (TILE_B)
#define ST_B0 (2 * TILE_B)
#define ST_B1 (3 * TILE_B)
#define STAGE_B (4 * TILE_B)         // 40960
#define GEMM_SMEM (2 * STAGE_B)      // 81920

// ---------------------------------------------------------------------------
// Device scratch
// ---------------------------------------------------------------------------
__device__ __align__(16) __nv_bfloat16 g_a0[(size_t)M_ROWS * D_MODEL];
__device__ __align__(16) __nv_bfloat16 g_a1[(size_t)M_ROWS * D_MODEL];
__device__ __align__(16) __nv_bfloat16 g_b0[(size_t)N_LAT * D_MODEL];
__device__ __align__(16) __nv_bfloat16 g_b1[(size_t)N_LAT * D_MODEL];
__device__ float g_WdecT[(size_t)N_LAT * D_MODEL];
__device__ int   g_cand[(size_t)M_ROWS * NCAND];
__device__ int   g_tk_idx[(size_t)M_ROWS * TOPK];
__device__ float g_tk_val[(size_t)M_ROWS * TOPK];

// ---------------------------------------------------------------------------
// PTX helpers (baseline sm_80+ features only: cp.async / ldmatrix / mma.sync)
// ---------------------------------------------------------------------------
__device__ __forceinline__ uint32_t smem_u32(const void* p) {
    uint32_t a;
    asm("{ .reg .u64 t; cvta.to.shared.u64 t, %1; cvt.u32.u64 %0, t; }"
        : "=r"(a) : "l"(p));
    return a;
}

__device__ __forceinline__ void cp16(uint32_t dst, const void* src) {
    asm volatile("cp.async.cg.shared.global [%0], [%1], 16;"
                 :: "r"(dst), "l"(src) : "memory");
}
__device__ __forceinline__ void cp_commit() {
    asm volatile("cp.async.commit_group;" ::: "memory");
}
template <int N>
__device__ __forceinline__ void cp_wait() {
    asm volatile("cp.async.wait_group %0;" :: "n"(N) : "memory");
}

__device__ __forceinline__ void ldsm4(uint32_t* r, uint32_t addr) {
    asm volatile("ldmatrix.sync.aligned.m8n8.x4.shared.b16 {%0,%1,%2,%3}, [%4];"
                 : "=r"(r[0]), "=r"(r[1]), "=r"(r[2]), "=r"(r[3]) : "r"(addr));
}
__device__ __forceinline__ void ldsm2(uint32_t* r, uint32_t addr) {
    asm volatile("ldmatrix.sync.aligned.m8n8.x2.shared.b16 {%0,%1}, [%2];"
                 : "=r"(r[0]), "=r"(r[1]) : "r"(addr));
}
__device__ __forceinline__ void mma16816(float* c, const uint32_t* a, const uint32_t* b) {
    asm volatile(
        "mma.sync.aligned.m16n8k16.row.col.f32.bf16.bf16.f32 "
        "{%0,%1,%2,%3}, {%4,%5,%6,%7}, {%8,%9}, {%0,%1,%2,%3};"
        : "+f"(c[0]), "+f"(c[1]), "+f"(c[2]), "+f"(c[3])
        : "r"(a[0]), "r"(a[1]), "r"(a[2]), "r"(a[3]), "r"(b[0]), "r"(b[1]));
}

// ---------------------------------------------------------------------------
// Kernel: bf16 two-term splits (write device globals directly)
// ---------------------------------------------------------------------------
__global__ void split_x_kernel(const float* __restrict__ src, int n)
{
    int i = blockIdx.x * blockDim.x + threadIdx.x;
    if (i < n) {
        float v = src[i];
        __nv_bfloat16 h0 = __float2bfloat16(v);
        g_a0[i] = h0;
        g_a1[i] = __float2bfloat16(v - __bfloat162float(h0));
    }
}
__global__ void split_w_kernel(const float* __restrict__ src, int n)
{
    int i = blockIdx.x * blockDim.x + threadIdx.x;
    if (i < n) {
        float v = src[i];
        __nv_bfloat16 h0 = __float2bfloat16(v);
        g_b0[i] = h0;
        g_b1[i] = __float2bfloat16(v - __bfloat162float(h0));
    }
}

// ---------------------------------------------------------------------------
// Kernel: encoder GEMM via mma.sync bf16x3.
// pre[M, N_LAT] ~= (a0+a1)(b0+b1)^T + bias (dropping a1*b1 term).
// ---------------------------------------------------------------------------
__global__ void __launch_bounds__(256, 2) gemm_enc_mma(
    const float* __restrict__ bias, float* __restrict__ C)
{
    extern __shared__ char smp[];
    const uint32_t sb = smem_u32(smp);
    __shared__ float sBias[BN];

    const int tid  = threadIdx.x;
    const int wid  = tid >> 5;
    const int lane = tid & 31;
    const int wm   = wid & 1;        // 2 warps along M (64 rows each)
    const int wn   = wid >> 1;       // 4 warps along N (32 cols each)
    const int bm   = blockIdx.y * BM;
    const int bn   = blockIdx.x * BN;

    if (tid < BN) sBias[tid] = bias[bn + tid];

    // per-lane fragment address offsets (within a tile, bytes)
    const int q  = lane >> 3;
    const int lr = lane & 7;
    int rbA[4], rbB[4];
    #pragma unroll
    for (int i = 0; i < 4; ++i)
        rbA[i] = (wm * 64 + i * 16 + (q & 1) * 8 + lr) * ROWB + (q >> 1) * 16;
    const int lp   = lane & 15;
    const int half = lp >> 3;
    const int lrB  = lp & 7;
    #pragma unroll
    for (int j = 0; j < 4; ++j)
        rbB[j] = (wn * 32 + j * 8 + lrB) * ROWB + half * 16;

    float acc[4][4][4];
    #pragma unroll
    for (int i = 0; i < 4; ++i)
        #pragma unroll
        for (int j = 0; j < 4; ++j)
            #pragma unroll
            for (int k = 0; k < 4; ++k)
                acc[i][j][k] = 0.0f;

    const int r0 = tid >> 2, s0 = tid & 3;
    const int r1 = r0 + 64;

    auto cp_chunk = [&](int c, int st) {
        const int kt = c * BK;
        const uint32_t base = sb + st * STAGE_B;
        {
            uint32_t d = base + r0 * ROWB + s0 * 16;
            size_t ga = (size_t)(bm + r0) * D_MODEL + kt + s0 * 8;
            size_t gb = (size_t)(bn + r0) * D_MODEL + kt + s0 * 8;
            cp16(d + ST_A0, g_a0 + ga);
            cp16(d + ST_A1, g_a1 + ga);
            cp16(d + ST_B0, g_b0 + gb);
            cp16(d + ST_B1, g_b1 + gb);
        }
        {
            uint32_t d = base + r1 * ROWB + s0 * 16;
            size_t ga = (size_t)(bm + r1) * D_MODEL + kt + s0 * 8;
            size_t gb = (size_t)(bn + r1) * D_MODEL + kt + s0 * 8;
            cp16(d + ST_A0, g_a0 + ga);
            cp16(d + ST_A1, g_a1 + ga);
            cp16(d + ST_B0, g_b0 + gb);
            cp16(d + ST_B1, g_b1 + gb);
        }
        cp_commit();
    };

    cp_chunk(0, 0);

    for (int c = 0; c < KCHUNKS; ++c) {
        if (c + 1 < KCHUNKS) {
            cp_chunk(c + 1, (c + 1) & 1);
            cp_wait<1>();
        } else {
            cp_wait<0>();
        }
        __syncthreads();

        const uint32_t base = sb + (c & 1) * STAGE_B;
        #pragma unroll
        for (int s = 0; s < 2; ++s) {
            const int so = s * 32;
            uint32_t a0f[4][4], a1f[4][4], bf[4][2];
            #pragma unroll
            for (int i = 0; i < 4; ++i) ldsm4(a0f[i], base + ST_A0 + rbA[i] + so);
            #pragma unroll
            for (int i = 0; i < 4; ++i) ldsm4(a1f[i], base + ST_A1 + rbA[i] + so);
            #pragma unroll
            for (int j = 0; j < 4; ++j) ldsm2(bf[j], base + ST_B0 + rbB[j] + so);
            #pragma unroll
            for (int i = 0; i < 4; ++i)
                #pragma unroll
                for (int j = 0; j < 4; ++j) mma16816(acc[i][j], a0f[i], bf[j]);
            #pragma unroll
            for (int i = 0; i < 4; ++i)
                #pragma unroll
                for (int j = 0; j < 4; ++j) mma16816(acc[i][j], a1f[i], bf[j]);
            #pragma unroll
            for (int j = 0; j < 4; ++j) ldsm2(bf[j], base + ST_B1 + rbB[j] + so);
            #pragma unroll
            for (int i = 0; i < 4; ++i)
                #pragma unroll
                for (int j = 0; j < 4; ++j) mma16816(acc[i][j], a0f[i], bf[j]);
        }
        __syncthreads();
    }

    const int er = lane >> 2;
    const int ec = (lane & 3) * 2;
    #pragma unroll
    for (int i = 0; i < 4; ++i) {
        const int row = bm + wm * 64 + i * 16 + er;
        #pragma unroll
        for (int j = 0; j < 4; ++j) {
            const int colb = wn * 32 + j * 8 + ec;
            const float bz0 = sBias[colb], bz1 = sBias[colb + 1];
            float2 v0 = make_float2(acc[i][j][0] + bz0, acc[i][j][1] + bz1);
            float2 v1 = make_float2(acc[i][j][2] + bz0, acc[i][j][3] + bz1);
            *(float2*)(C + (size_t)row * N_LAT + bn + colb)       = v0;
            *(float2*)(C + (size_t)(row + 8) * N_LAT + bn + colb) = v1;
        }
    }
}

// ---------------------------------------------------------------------------
// Kernel: W_dec [D_MODEL, N_LAT] -> g_WdecT [N_LAT, D_MODEL]
// ---------------------------------------------------------------------------
__global__ void transpose_kernel(const float* __restrict__ Wdec)
{
    __shared__ float tile[32][33];
    const int l  = blockIdx.x * 32 + threadIdx.x;
    const int d0 = blockIdx.y * 32;
    #pragma unroll
    for (int j = threadIdx.y; j < 32; j += 8)
        tile[j][threadIdx.x] = Wdec[(size_t)(d0 + j) * N_LAT + l];
    __syncthreads();
    const int d  = d0 + threadIdx.x;
    const int l0 = blockIdx.x * 32;
    #pragma unroll
    for (int j = threadIdx.y; j < 32; j += 8)
        g_WdecT[(size_t)(l0 + j) * D_MODEL + d] = tile[threadIdx.x][j];
}

// ---------------------------------------------------------------------------
// Kernel: top-NCAND candidates per row via 4-pass radix select (approx pre).
// ---------------------------------------------------------------------------
__global__ void topk_kernel(const float* __restrict__ pre)
{
    extern __shared__ unsigned skeys[];
    __shared__ unsigned hist[256];
    __shared__ unsigned s_prefix, s_remk;

    const int row = blockIdx.x;
    const float* prow = pre + (size_t)row * N_LAT;
    const int tid = threadIdx.x;

    for (int i = tid; i < N_LAT; i += 256) {
        unsigned u = __float_as_uint(prow[i]);
        skeys[i] = (u & 0x80000000u) ? ~u : (u | 0x80000000u);
    }
    __syncthreads();

    unsigned prefix = 0u, remk = NCAND;
    for (int shift = 24; shift >= 0; shift -= 8) {
        const unsigned mask_hi = (shift == 24) ? 0u : (0xFFFFFFFFu << (shift + 8));
        hist[tid] = 0u;
        __syncthreads();
        for (int i = tid; i < N_LAT; i += 256) {
            unsigned k = skeys[i];
            if ((k & mask_hi) == prefix)
                atomicAdd(&hist[(k >> shift) & 0xFFu], 1u);
        }
        __syncthreads();
        if (tid == 0) {
            unsigned cum = 0; int b = 255;
            for (; b > 0; --b) {
                if (cum + hist[b] >= remk) break;
                cum += hist[b];
            }
            s_prefix = prefix | ((unsigned)b << shift);
            s_remk   = remk - cum;
        }
        __syncthreads();
        prefix = s_prefix;
        remk   = s_remk;
        __syncthreads();
    }

    const unsigned T = prefix;
    if (tid < 32) {
        unsigned taken = 0, need_eq = remk;
        const unsigned lmask = (1u << tid) - 1u;
        for (int base = 0; base < N_LAT && taken < NCAND; base += 32) {
            const unsigned k = skeys[base + tid];
            const bool gt = (k > T);
            const bool eq = (k == T);
            const unsigned bg = __ballot_sync(0xFFFFFFFFu, gt);
            const unsigned be = __ballot_sync(0xFFFFFFFFu, eq);
            const unsigned ng = __popc(bg);
            const unsigned ne = __popc(be);
            const unsigned take_eq = (ne < need_eq) ? ne : need_eq;
            int slot = -1;
            if (gt) {
                slot = (int)(taken + __popc(bg & lmask));
            } else if (eq) {
                const unsigned r = __popc(be & lmask);
                if (r < take_eq) slot = (int)(taken + ng + r);
            }
            if (slot >= 0 && slot < NCAND)
                g_cand[(size_t)row * NCAND + slot] = base + tid;
            taken   += ng + take_eq;
            need_eq -= take_eq;
        }
    }
}

// ---------------------------------------------------------------------------
// Kernel: exact fp32 re-rank, sequential-k accumulation (matches R1 ordering).
// One thread per candidate: single dependent fmaf chain k = 0..767.
// ---------------------------------------------------------------------------
__global__ void __launch_bounds__(NCAND) rerank_kernel(
    const float* __restrict__ x, const float* __restrict__ W_enc,
    const float* __restrict__ b_enc, float* __restrict__ latents)
{
    __shared__ float sx[D_MODEL];
    __shared__ float sval[NCAND];
    __shared__ int   sidx[NCAND];

    const int row = blockIdx.x;
    const int tid = threadIdx.x;

    for (int i = tid; i < D_MODEL; i += NCAND)
        sx[i] = x[(size_t)row * D_MODEL + i];
    sidx[tid] = g_cand[(size_t)row * NCAND + tid];
    __syncthreads();

    const int idx = sidx[tid];
    const float* __restrict__ wrow = W_enc + (size_t)idx * D_MODEL;
    float acc = 0.0f;
    #pragma unroll 16
    for (int k = 0; k < D_MODEL; ++k)
        acc = fmaf(sx[k], __ldg(wrow + k), acc);   // strictly sequential chain
    sval[tid] = acc + b_enc[idx];
    __syncthreads();

    // rank among NCAND (ties -> smaller index first, matching lax.top_k)
    const float v = sval[tid];
    int rank = 0;
    #pragma unroll
    for (int j = 0; j < NCAND; ++j) {
        const float vj = sval[j];
        rank += (vj > v) || (vj == v && sidx[j] < idx);
    }
    if (rank < TOPK) {
        const float rv = fmaxf(v, 0.0f);
        g_tk_idx[(size_t)row * TOPK + rank] = idx;
        g_tk_val[(size_t)row * TOPK + rank] = rv;
        latents[(size_t)row * N_LAT + idx] = rv;
    }
}

// ---------------------------------------------------------------------------
// Kernel: sparse decode
// ---------------------------------------------------------------------------
__global__ void __launch_bounds__(256) decode_kernel(
    const float* __restrict__ b_dec, float* __restrict__ rec)
{
    const int row = blockIdx.x;
    __shared__ int   sidx[TOPK];
    __shared__ float sval[TOPK];
    const int tid = threadIdx.x;
    if (tid < TOPK) {
        sidx[tid] = g_tk_idx[(size_t)row * TOPK + tid];
        sval[tid] = g_tk_val[(size_t)row * TOPK + tid];
    }
    __syncthreads();
    for (int d = tid; d < D_MODEL; d += 256) {
        float acc = b_dec[d];
        #pragma unroll
        for (int j = 0; j < TOPK; ++j)
            acc = fmaf(sval[j], g_WdecT[(size_t)sidx[j] * D_MODEL + d], acc);
        rec[(size_t)row * D_MODEL + d] = acc;
    }
}

// ---------------------------------------------------------------------------
// Launch
// ---------------------------------------------------------------------------
extern "C" void kernel_launch(void* const* d_in, const int* in_sizes, int n_in,
                              void* d_out, int out_size)
{
    const float* x     = (const float*)d_in[0];
    const float* W_enc = (const float*)d_in[1];
    const float* b_enc = (const float*)d_in[2];
    const float* W_dec = (const float*)d_in[3];
    const float* b_dec = (const float*)d_in[4];

    float* out = (float*)d_out;
    const size_t LAT_ELEMS = (size_t)M_ROWS * N_LAT;
    const size_t REC_ELEMS = (size_t)M_ROWS * D_MODEL;
    float* latents = out;
    float* rec     = out + LAT_ELEMS;
    float* pre     = out + LAT_ELEMS + REC_ELEMS;

    cudaFuncSetAttribute(gemm_enc_mma, cudaFuncAttributeMaxDynamicSharedMemorySize, GEMM_SMEM);
    cudaFuncSetAttribute(topk_kernel, cudaFuncAttributeMaxDynamicSharedMemorySize, 65536);

    const int n_x = M_ROWS * D_MODEL;
    const int n_w = N_LAT * D_MODEL;
    split_x_kernel<<<(n_x + 255) / 256, 256>>>(x, n_x);
    split_w_kernel<<<(n_w + 255) / 256, 256>>>(W_enc, n_w);

    cudaMemsetAsync(latents, 0, LAT_ELEMS * sizeof(float), 0);

    gemm_enc_mma<<<dim3(N_LAT / BN, M_ROWS / BM), 256, GEMM_SMEM>>>(b_enc, pre);

    transpose_kernel<<<dim3(N_LAT / 32, D_MODEL / 32), dim3(32, 8)>>>(W_dec);

    topk_kernel<<<M_ROWS, 256, 65536>>>(pre);

    rerank_kernel<<<M_ROWS, NCAND>>>(x, W_enc, b_enc, latents);

    decode_kernel<<<M_ROWS, 256>>>(b_dec, rec);
}

// round 5
// speedup vs baseline: 1.3061x; 1.0031x over previous
#include <cuda_runtime.h>
#include <cuda_bf16.h>
#include <stdint.h>

#define M_ROWS 8192
#define D_MODEL 768
#define N_LAT 16384
#define TOPK 32
#define NCAND 64

// GEMM tiling (mma.sync path)
#define BM 128
#define BN 256
#define BK 32
#define KCHUNKS (D_MODEL / BK)       // 24
#define ROWB 80                       // padded row stride in bytes (40 bf16)
#define ST_A0 0
#define ST_A1 (128 * ROWB)            // 10240
#define ST_B0 (2 * 128 * ROWB)        // 20480
#define ST_B1 (ST_B0 + 256 * ROWB)    // 40960
#define STAGE_B (ST_B1 + 256 * ROWB)  // 61440
#define NSTAGE 3
#define GEMM_SMEM (NSTAGE * STAGE_B)  // 184320

// ---------------------------------------------------------------------------
// Device scratch
// ---------------------------------------------------------------------------
__device__ __align__(16) __nv_bfloat16 g_a0[(size_t)M_ROWS * D_MODEL];
__device__ __align__(16) __nv_bfloat16 g_a1[(size_t)M_ROWS * D_MODEL];
__device__ __align__(16) __nv_bfloat16 g_b0[(size_t)N_LAT * D_MODEL];
__device__ __align__(16) __nv_bfloat16 g_b1[(size_t)N_LAT * D_MODEL];
__device__ float g_WdecT[(size_t)N_LAT * D_MODEL];
__device__ int   g_cand[(size_t)M_ROWS * NCAND];
__device__ int   g_tk_idx[(size_t)M_ROWS * TOPK];
__device__ float g_tk_val[(size_t)M_ROWS * TOPK];

// ---------------------------------------------------------------------------
// PTX helpers (baseline sm_80+ features only)
// ---------------------------------------------------------------------------
__device__ __forceinline__ uint32_t smem_u32(const void* p) {
    uint32_t a;
    asm("{ .reg .u64 t; cvta.to.shared.u64 t, %1; cvt.u32.u64 %0, t; }"
        : "=r"(a) : "l"(p));
    return a;
}
__device__ __forceinline__ void cp16(uint32_t dst, const void* src) {
    asm volatile("cp.async.cg.shared.global [%0], [%1], 16;"
                 :: "r"(dst), "l"(src) : "memory");
}
__device__ __forceinline__ void cp_commit() {
    asm volatile("cp.async.commit_group;" ::: "memory");
}
template <int N>
__device__ __forceinline__ void cp_wait() {
    asm volatile("cp.async.wait_group %0;" :: "n"(N) : "memory");
}
__device__ __forceinline__ void ldsm4(uint32_t* r, uint32_t addr) {
    asm volatile("ldmatrix.sync.aligned.m8n8.x4.shared.b16 {%0,%1,%2,%3}, [%4];"
                 : "=r"(r[0]), "=r"(r[1]), "=r"(r[2]), "=r"(r[3]) : "r"(addr));
}
__device__ __forceinline__ void mma16816(float* c, const uint32_t* a, const uint32_t* b) {
    asm volatile(
        "mma.sync.aligned.m16n8k16.row.col.f32.bf16.bf16.f32 "
        "{%0,%1,%2,%3}, {%4,%5,%6,%7}, {%8,%9}, {%0,%1,%2,%3};"
        : "+f"(c[0]), "+f"(c[1]), "+f"(c[2]), "+f"(c[3])
        : "r"(a[0]), "r"(a[1]), "r"(a[2]), "r"(a[3]), "r"(b[0]), "r"(b[1]));
}

// ---------------------------------------------------------------------------
// Kernels: bf16 two-term splits
// ---------------------------------------------------------------------------
__global__ void split_x_kernel(const float* __restrict__ src, int n)
{
    int i = blockIdx.x * blockDim.x + threadIdx.x;
    if (i < n) {
        float v = src[i];
        __nv_bfloat16 h0 = __float2bfloat16(v);
        g_a0[i] = h0;
        g_a1[i] = __float2bfloat16(v - __bfloat162float(h0));
    }
}
__global__ void split_w_kernel(const float* __restrict__ src, int n)
{
    int i = blockIdx.x * blockDim.x + threadIdx.x;
    if (i < n) {
        float v = src[i];
        __nv_bfloat16 h0 = __float2bfloat16(v);
        g_b0[i] = h0;
        g_b1[i] = __float2bfloat16(v - __bfloat162float(h0));
    }
}

// ---------------------------------------------------------------------------
// Kernel: encoder GEMM via mma.sync bf16x3, 128x256 CTA tile, 64x64 warp tile,
// 3-stage cp.async pipeline, 1 CTA/SM (no register spills).
// ---------------------------------------------------------------------------
__global__ void __launch_bounds__(256, 1) gemm_enc_mma(
    const float* __restrict__ bias, float* __restrict__ C)
{
    extern __shared__ char smp[];
    const uint32_t sb = smem_u32(smp);
    __shared__ float sBias[BN];

    const int tid  = threadIdx.x;
    const int wid  = tid >> 5;
    const int lane = tid & 31;
    const int wm   = wid & 1;        // 2 warps along M (64 rows each)
    const int wn   = wid >> 1;       // 4 warps along N (64 cols each)
    const int bm   = blockIdx.y * BM;
    const int bn   = blockIdx.x * BN;

    if (tid < BN) sBias[tid] = bias[bn + tid];

    // A ldmatrix.x4 addressing: 4 m16 tiles per warp
    const int q  = lane >> 3;
    const int lr = lane & 7;
    int rbA[4];
    #pragma unroll
    for (int i = 0; i < 4; ++i)
        rbA[i] = (wm * 64 + i * 16 + (q & 1) * 8 + lr) * ROWB + (q >> 1) * 16;
    // B ldmatrix.x4 addressing: pair p covers n8 tiles 2p, 2p+1
    // lanes 0-7: tile 2p khalf0; 8-15: tile 2p khalf1; 16-23: tile 2p+1 khalf0; 24-31: khalf1
    int rbB[4];
    #pragma unroll
    for (int p = 0; p < 4; ++p)
        rbB[p] = (wn * 64 + (2 * p + (lane >> 4)) * 8 + lr) * ROWB + ((lane >> 3) & 1) * 16;

    float acc[4][8][4];
    #pragma unroll
    for (int i = 0; i < 4; ++i)
        #pragma unroll
        for (int j = 0; j < 8; ++j)
            #pragma unroll
            for (int k = 0; k < 4; ++k)
                acc[i][j][k] = 0.0f;

    // cp.async: 3072 cp16 per chunk (768 rows x 4 segs), 12 per thread
    auto cp_chunk = [&](int c, int st) {
        const int kt = c * BK;
        const uint32_t base = sb + st * STAGE_B;
        #pragma unroll
        for (int i = 0; i < 12; ++i) {
            const int u   = tid + 256 * i;
            const int seg = u & 3;
            const int r   = u >> 2;
            if (r < 256) {
                const int rr = r & 127;
                const __nv_bfloat16* src =
                    (r < 128 ? g_a0 : g_a1) + (size_t)(bm + rr) * D_MODEL + kt + seg * 8;
                cp16(base + (r < 128 ? ST_A0 : ST_A1) + rr * ROWB + seg * 16, src);
            } else {
                const int rr = (r - 256) & 255;
                const __nv_bfloat16* src =
                    (r < 512 ? g_b0 : g_b1) + (size_t)(bn + rr) * D_MODEL + kt + seg * 8;
                cp16(base + (r < 512 ? ST_B0 : ST_B1) + rr * ROWB + seg * 16, src);
            }
        }
        cp_commit();
    };

    cp_chunk(0, 0);
    cp_chunk(1, 1);

    for (int c = 0; c < KCHUNKS; ++c) {
        if (c < KCHUNKS - 1) cp_wait<1>(); else cp_wait<0>();
        __syncthreads();
        if (c + 2 < KCHUNKS) cp_chunk(c + 2, (c + 2) % NSTAGE);

        const uint32_t base = sb + (c % NSTAGE) * STAGE_B;
        #pragma unroll
        for (int s = 0; s < 2; ++s) {
            const int so = s * 32;
            uint32_t a0f[4][4], a1f[4][4], bfr[8][2];
            #pragma unroll
            for (int i = 0; i < 4; ++i) ldsm4(a0f[i], base + ST_A0 + rbA[i] + so);
            #pragma unroll
            for (int p = 0; p < 4; ++p) {
                uint32_t t[4];
                ldsm4(t, base + ST_B0 + rbB[p] + so);
                bfr[2*p][0] = t[0]; bfr[2*p][1] = t[1];
                bfr[2*p+1][0] = t[2]; bfr[2*p+1][1] = t[3];
            }
            #pragma unroll
            for (int i = 0; i < 4; ++i)
                #pragma unroll
                for (int j = 0; j < 8; ++j) mma16816(acc[i][j], a0f[i], bfr[j]);
            #pragma unroll
            for (int i = 0; i < 4; ++i) ldsm4(a1f[i], base + ST_A1 + rbA[i] + so);
            #pragma unroll
            for (int i = 0; i < 4; ++i)
                #pragma unroll
                for (int j = 0; j < 8; ++j) mma16816(acc[i][j], a1f[i], bfr[j]);
            #pragma unroll
            for (int p = 0; p < 4; ++p) {
                uint32_t t[4];
                ldsm4(t, base + ST_B1 + rbB[p] + so);
                bfr[2*p][0] = t[0]; bfr[2*p][1] = t[1];
                bfr[2*p+1][0] = t[2]; bfr[2*p+1][1] = t[3];
            }
            #pragma unroll
            for (int i = 0; i < 4; ++i)
                #pragma unroll
                for (int j = 0; j < 8; ++j) mma16816(acc[i][j], a0f[i], bfr[j]);
        }
        __syncthreads();
    }

    // epilogue
    const int er = lane >> 2;
    const int ec = (lane & 3) * 2;
    #pragma unroll
    for (int i = 0; i < 4; ++i) {
        const int row = bm + wm * 64 + i * 16 + er;
        float* crow0 = C + (size_t)row * N_LAT + bn + wn * 64;
        float* crow1 = crow0 + (size_t)8 * N_LAT;
        #pragma unroll
        for (int j = 0; j < 8; ++j) {
            const int colb = j * 8 + ec;
            const float bz0 = sBias[wn * 64 + colb];
            const float bz1 = sBias[wn * 64 + colb + 1];
            float2 v0 = make_float2(acc[i][j][0] + bz0, acc[i][j][1] + bz1);
            float2 v1 = make_float2(acc[i][j][2] + bz0, acc[i][j][3] + bz1);
            *(float2*)(crow0 + colb) = v0;
            *(float2*)(crow1 + colb) = v1;
        }
    }
}

// ---------------------------------------------------------------------------
// Kernel: W_dec [D_MODEL, N_LAT] -> g_WdecT [N_LAT, D_MODEL]
// ---------------------------------------------------------------------------
__global__ void transpose_kernel(const float* __restrict__ Wdec)
{
    __shared__ float tile[32][33];
    const int l  = blockIdx.x * 32 + threadIdx.x;
    const int d0 = blockIdx.y * 32;
    #pragma unroll
    for (int j = threadIdx.y; j < 32; j += 8)
        tile[j][threadIdx.x] = Wdec[(size_t)(d0 + j) * N_LAT + l];
    __syncthreads();
    const int d  = d0 + threadIdx.x;
    const int l0 = blockIdx.x * 32;
    #pragma unroll
    for (int j = threadIdx.y; j < 32; j += 8)
        g_WdecT[(size_t)(l0 + j) * D_MODEL + d] = tile[threadIdx.x][j];
}

// ---------------------------------------------------------------------------
// Kernel: top-NCAND candidates per row via 4-pass radix select (approx pre).
// ---------------------------------------------------------------------------
__global__ void topk_kernel(const float* __restrict__ pre)
{
    extern __shared__ unsigned skeys[];
    __shared__ unsigned hist[256];
    __shared__ unsigned s_prefix, s_remk;

    const int row = blockIdx.x;
    const float* prow = pre + (size_t)row * N_LAT;
    const int tid = threadIdx.x;

    for (int i = tid; i < N_LAT; i += 256) {
        unsigned u = __float_as_uint(prow[i]);
        skeys[i] = (u & 0x80000000u) ? ~u : (u | 0x80000000u);
    }
    __syncthreads();

    unsigned prefix = 0u, remk = NCAND;
    for (int shift = 24; shift >= 0; shift -= 8) {
        const unsigned mask_hi = (shift == 24) ? 0u : (0xFFFFFFFFu << (shift + 8));
        hist[tid] = 0u;
        __syncthreads();
        for (int i = tid; i < N_LAT; i += 256) {
            unsigned k = skeys[i];
            if ((k & mask_hi) == prefix)
                atomicAdd(&hist[(k >> shift) & 0xFFu], 1u);
        }
        __syncthreads();
        if (tid == 0) {
            unsigned cum = 0; int b = 255;
            for (; b > 0; --b) {
                if (cum + hist[b] >= remk) break;
                cum += hist[b];
            }
            s_prefix = prefix | ((unsigned)b << shift);
            s_remk   = remk - cum;
        }
        __syncthreads();
        prefix = s_prefix;
        remk   = s_remk;
        __syncthreads();
    }

    const unsigned T = prefix;
    if (tid < 32) {
        unsigned taken = 0, need_eq = remk;
        const unsigned lmask = (1u << tid) - 1u;
        for (int base = 0; base < N_LAT && taken < NCAND; base += 32) {
            const unsigned k = skeys[base + tid];
            const bool gt = (k > T);
            const bool eq = (k == T);
            const unsigned bg = __ballot_sync(0xFFFFFFFFu, gt);
            const unsigned be = __ballot_sync(0xFFFFFFFFu, eq);
            const unsigned ng = __popc(bg);
            const unsigned ne = __popc(be);
            const unsigned take_eq = (ne < need_eq) ? ne : need_eq;
            int slot = -1;
            if (gt) {
                slot = (int)(taken + __popc(bg & lmask));
            } else if (eq) {
                const unsigned r = __popc(be & lmask);
                if (r < take_eq) slot = (int)(taken + ng + r);
            }
            if (slot >= 0 && slot < NCAND)
                g_cand[(size_t)row * NCAND + slot] = base + tid;
            taken   += ng + take_eq;
            need_eq -= take_eq;
        }
    }
}

// ---------------------------------------------------------------------------
// Kernel: exact fp32 re-rank, strictly sequential k accumulation.
// ---------------------------------------------------------------------------
__global__ void __launch_bounds__(NCAND) rerank_kernel(
    const float* __restrict__ x, const float* __restrict__ W_enc,
    const float* __restrict__ b_enc, float* __restrict__ latents)
{
    __shared__ float sx[D_MODEL];
    __shared__ float sval[NCAND];
    __shared__ int   sidx[NCAND];

    const int row = blockIdx.x;
    const int tid = threadIdx.x;

    for (int i = tid; i < D_MODEL; i += NCAND)
        sx[i] = x[(size_t)row * D_MODEL + i];
    sidx[tid] = g_cand[(size_t)row * NCAND + tid];
    __syncthreads();

    const int idx = sidx[tid];
    const float* __restrict__ wrow = W_enc + (size_t)idx * D_MODEL;
    float acc = 0.0f;
    #pragma unroll 16
    for (int k = 0; k < D_MODEL; ++k)
        acc = fmaf(sx[k], __ldg(wrow + k), acc);
    sval[tid] = acc + b_enc[idx];
    __syncthreads();

    const float v = sval[tid];
    int rank = 0;
    #pragma unroll
    for (int j = 0; j < NCAND; ++j) {
        const float vj = sval[j];
        rank += (vj > v) || (vj == v && sidx[j] < idx);
    }
    if (rank < TOPK) {
        const float rv = fmaxf(v, 0.0f);
        g_tk_idx[(size_t)row * TOPK + rank] = idx;
        g_tk_val[(size_t)row * TOPK + rank] = rv;
        latents[(size_t)row * N_LAT + idx] = rv;
    }
}

// ---------------------------------------------------------------------------
// Kernel: sparse decode
// ---------------------------------------------------------------------------
__global__ void __launch_bounds__(256) decode_kernel(
    const float* __restrict__ b_dec, float* __restrict__ rec)
{
    const int row = blockIdx.x;
    __shared__ int   sidx[TOPK];
    __shared__ float sval[TOPK];
    const int tid = threadIdx.x;
    if (tid < TOPK) {
        sidx[tid] = g_tk_idx[(size_t)row * TOPK + tid];
        sval[tid] = g_tk_val[(size_t)row * TOPK + tid];
    }
    __syncthreads();
    for (int d = tid; d < D_MODEL; d += 256) {
        float acc = b_dec[d];
        #pragma unroll
        for (int j = 0; j < TOPK; ++j)
            acc = fmaf(sval[j], g_WdecT[(size_t)sidx[j] * D_MODEL + d], acc);
        rec[(size_t)row * D_MODEL + d] = acc;
    }
}

// ---------------------------------------------------------------------------
// Launch (transpose moved before GEMM so ncu -s 5 captures the GEMM)
// ---------------------------------------------------------------------------
extern "C" void kernel_launch(void* const* d_in, const int* in_sizes, int n_in,
                              void* d_out, int out_size)
{
    const float* x     = (const float*)d_in[0];
    const float* W_enc = (const float*)d_in[1];
    const float* b_enc = (const float*)d_in[2];
    const float* W_dec = (const float*)d_in[3];
    const float* b_dec = (const float*)d_in[4];

    float* out = (float*)d_out;
    const size_t LAT_ELEMS = (size_t)M_ROWS * N_LAT;
    const size_t REC_ELEMS = (size_t)M_ROWS * D_MODEL;
    float* latents = out;
    float* rec     = out + LAT_ELEMS;
    float* pre     = out + LAT_ELEMS + REC_ELEMS;

    cudaFuncSetAttribute(gemm_enc_mma, cudaFuncAttributeMaxDynamicSharedMemorySize, GEMM_SMEM);
    cudaFuncSetAttribute(topk_kernel, cudaFuncAttributeMaxDynamicSharedMemorySize, 65536);

    const int n_x = M_ROWS * D_MODEL;
    const int n_w = N_LAT * D_MODEL;
    split_x_kernel<<<(n_x + 255) / 256, 256>>>(x, n_x);          // launch 1
    split_w_kernel<<<(n_w + 255) / 256, 256>>>(W_enc, n_w);      // launch 2

    cudaMemsetAsync(latents, 0, LAT_ELEMS * sizeof(float), 0);   // launch 3

    transpose_kernel<<<dim3(N_LAT / 32, D_MODEL / 32), dim3(32, 8)>>>(W_dec);  // launch 4

    gemm_enc_mma<<<dim3(N_LAT / BN, M_ROWS / BM), 256, GEMM_SMEM>>>(b_enc, pre); // launch 5/6

    topk_kernel<<<M_ROWS, 256, 65536>>>(pre);

    rerank_kernel<<<M_ROWS, NCAND>>>(x, W_enc, b_enc, latents);

    decode_kernel<<<M_ROWS, 256>>>(b_dec, rec);
}

// round 6
// speedup vs baseline: 1.6412x; 1.2566x over previous
#include <cuda_runtime.h>
#include <cuda_bf16.h>
#include <stdint.h>

#define M_ROWS 8192
#define D_MODEL 768
#define N_LAT 16384
#define TOPK 32
#define NCAND 64

// GEMM tiling (mma.sync path), 512 threads: 2x8 warps of 64x32 tiles
#define BM 128
#define BN 256
#define BK 32
#define KCHUNKS (D_MODEL / BK)       // 24
#define ROWB 80                       // padded row stride in bytes (40 bf16)
#define ST_A0 0
#define ST_A1 (128 * ROWB)            // 10240
#define ST_B0 (2 * 128 * ROWB)        // 20480
#define ST_B1 (ST_B0 + 256 * ROWB)    // 40960
#define STAGE_B (ST_B1 + 256 * ROWB)  // 61440
#define NSTAGE 3
#define GEMM_SMEM (NSTAGE * STAGE_B)  // 184320

// ---------------------------------------------------------------------------
// Device scratch
// ---------------------------------------------------------------------------
__device__ __align__(16) __nv_bfloat16 g_a0[(size_t)M_ROWS * D_MODEL];
__device__ __align__(16) __nv_bfloat16 g_a1[(size_t)M_ROWS * D_MODEL];
__device__ __align__(16) __nv_bfloat16 g_b0[(size_t)N_LAT * D_MODEL];
__device__ __align__(16) __nv_bfloat16 g_b1[(size_t)N_LAT * D_MODEL];
__device__ float g_WdecT[(size_t)N_LAT * D_MODEL];
__device__ int   g_cand[(size_t)M_ROWS * NCAND];
__device__ int   g_tk_idx[(size_t)M_ROWS * TOPK];
__device__ float g_tk_val[(size_t)M_ROWS * TOPK];

// ---------------------------------------------------------------------------
// PTX helpers (baseline sm_80+ features only)
// ---------------------------------------------------------------------------
__device__ __forceinline__ uint32_t smem_u32(const void* p) {
    uint32_t a;
    asm("{ .reg .u64 t; cvta.to.shared.u64 t, %1; cvt.u32.u64 %0, t; }"
        : "=r"(a) : "l"(p));
    return a;
}
__device__ __forceinline__ void cp16(uint32_t dst, const void* src) {
    asm volatile("cp.async.cg.shared.global [%0], [%1], 16;"
                 :: "r"(dst), "l"(src) : "memory");
}
__device__ __forceinline__ void cp_commit() {
    asm volatile("cp.async.commit_group;" ::: "memory");
}
template <int N>
__device__ __forceinline__ void cp_wait() {
    asm volatile("cp.async.wait_group %0;" :: "n"(N) : "memory");
}
__device__ __forceinline__ void ldsm4(uint32_t* r, uint32_t addr) {
    asm volatile("ldmatrix.sync.aligned.m8n8.x4.shared.b16 {%0,%1,%2,%3}, [%4];"
                 : "=r"(r[0]), "=r"(r[1]), "=r"(r[2]), "=r"(r[3]) : "r"(addr));
}
__device__ __forceinline__ void mma16816(float* c, const uint32_t* a, const uint32_t* b) {
    asm volatile(
        "mma.sync.aligned.m16n8k16.row.col.f32.bf16.bf16.f32 "
        "{%0,%1,%2,%3}, {%4,%5,%6,%7}, {%8,%9}, {%0,%1,%2,%3};"
        : "+f"(c[0]), "+f"(c[1]), "+f"(c[2]), "+f"(c[3])
        : "r"(a[0]), "r"(a[1]), "r"(a[2]), "r"(a[3]), "r"(b[0]), "r"(b[1]));
}

// ---------------------------------------------------------------------------
// Kernels: bf16 two-term splits
// ---------------------------------------------------------------------------
__global__ void split_x_kernel(const float* __restrict__ src, int n)
{
    int i = blockIdx.x * blockDim.x + threadIdx.x;
    if (i < n) {
        float v = src[i];
        __nv_bfloat16 h0 = __float2bfloat16(v);
        g_a0[i] = h0;
        g_a1[i] = __float2bfloat16(v - __bfloat162float(h0));
    }
}
__global__ void split_w_kernel(const float* __restrict__ src, int n)
{
    int i = blockIdx.x * blockDim.x + threadIdx.x;
    if (i < n) {
        float v = src[i];
        __nv_bfloat16 h0 = __float2bfloat16(v);
        g_b0[i] = h0;
        g_b1[i] = __float2bfloat16(v - __bfloat162float(h0));
    }
}

// ---------------------------------------------------------------------------
// Kernel: encoder GEMM, mma.sync bf16x3, 512 threads (16 warps), 64x32 warp
// tiles, 3-stage cp.async pipeline.
// ---------------------------------------------------------------------------
__global__ void __launch_bounds__(512, 1) gemm_enc_mma(
    const float* __restrict__ bias, float* __restrict__ C)
{
    extern __shared__ char smp[];
    const uint32_t sb = smem_u32(smp);
    __shared__ float sBias[BN];

    const int tid  = threadIdx.x;
    const int wid  = tid >> 5;
    const int lane = tid & 31;
    const int wm   = wid & 1;        // 2 warps along M (64 rows each)
    const int wn   = wid >> 1;       // 8 warps along N (32 cols each)
    const int bm   = blockIdx.y * BM;
    const int bn   = blockIdx.x * BN;

    if (tid < BN) sBias[tid] = bias[bn + tid];

    // A ldmatrix.x4 addressing: 4 m16 tiles per warp
    const int q  = lane >> 3;
    const int lr = lane & 7;
    int rbA[4];
    #pragma unroll
    for (int i = 0; i < 4; ++i)
        rbA[i] = (wm * 64 + i * 16 + (q & 1) * 8 + lr) * ROWB + (q >> 1) * 16;
    // B ldmatrix.x4 addressing: pair p covers n8 tiles 2p, 2p+1 (warp N=32 -> p<2)
    int rbB[2];
    #pragma unroll
    for (int p = 0; p < 2; ++p)
        rbB[p] = (wn * 32 + (2 * p + (lane >> 4)) * 8 + lr) * ROWB + ((lane >> 3) & 1) * 16;

    float acc[4][4][4];
    #pragma unroll
    for (int i = 0; i < 4; ++i)
        #pragma unroll
        for (int j = 0; j < 4; ++j)
            #pragma unroll
            for (int k = 0; k < 4; ++k)
                acc[i][j][k] = 0.0f;

    // cp.async: 3072 cp16 per chunk, 6 per thread
    auto cp_chunk = [&](int c, int st) {
        const int kt = c * BK;
        const uint32_t base = sb + st * STAGE_B;
        #pragma unroll
        for (int i = 0; i < 6; ++i) {
            const int u   = tid + 512 * i;
            const int seg = u & 3;
            const int r   = u >> 2;
            if (r < 256) {
                const int rr = r & 127;
                const __nv_bfloat16* src =
                    (r < 128 ? g_a0 : g_a1) + (size_t)(bm + rr) * D_MODEL + kt + seg * 8;
                cp16(base + (r < 128 ? ST_A0 : ST_A1) + rr * ROWB + seg * 16, src);
            } else {
                const int rr = (r - 256) & 255;
                const __nv_bfloat16* src =
                    (r < 512 ? g_b0 : g_b1) + (size_t)(bn + rr) * D_MODEL + kt + seg * 8;
                cp16(base + (r < 512 ? ST_B0 : ST_B1) + rr * ROWB + seg * 16, src);
            }
        }
        cp_commit();
    };

    cp_chunk(0, 0);
    cp_chunk(1, 1);

    for (int c = 0; c < KCHUNKS; ++c) {
        if (c < KCHUNKS - 1) cp_wait<1>(); else cp_wait<0>();
        __syncthreads();
        if (c + 2 < KCHUNKS) cp_chunk(c + 2, (c + 2) % NSTAGE);

        const uint32_t base = sb + (c % NSTAGE) * STAGE_B;
        #pragma unroll
        for (int s = 0; s < 2; ++s) {
            const int so = s * 32;
            uint32_t af[4][4], b0r[4][2], b1r[4][2];
            // load a0 + b0, pass 1: a0*b0
            #pragma unroll
            for (int i = 0; i < 4; ++i) ldsm4(af[i], base + ST_A0 + rbA[i] + so);
            #pragma unroll
            for (int p = 0; p < 2; ++p) {
                uint32_t t[4];
                ldsm4(t, base + ST_B0 + rbB[p] + so);
                b0r[2*p][0] = t[0]; b0r[2*p][1] = t[1];
                b0r[2*p+1][0] = t[2]; b0r[2*p+1][1] = t[3];
            }
            #pragma unroll
            for (int i = 0; i < 4; ++i)
                #pragma unroll
                for (int j = 0; j < 4; ++j) mma16816(acc[i][j], af[i], b0r[j]);
            // load b1, pass 2: a0*b1
            #pragma unroll
            for (int p = 0; p < 2; ++p) {
                uint32_t t[4];
                ldsm4(t, base + ST_B1 + rbB[p] + so);
                b1r[2*p][0] = t[0]; b1r[2*p][1] = t[1];
                b1r[2*p+1][0] = t[2]; b1r[2*p+1][1] = t[3];
            }
            #pragma unroll
            for (int i = 0; i < 4; ++i)
                #pragma unroll
                for (int j = 0; j < 4; ++j) mma16816(acc[i][j], af[i], b1r[j]);
            // load a1 (reuse af), pass 3: a1*b0
            #pragma unroll
            for (int i = 0; i < 4; ++i) ldsm4(af[i], base + ST_A1 + rbA[i] + so);
            #pragma unroll
            for (int i = 0; i < 4; ++i)
                #pragma unroll
                for (int j = 0; j < 4; ++j) mma16816(acc[i][j], af[i], b0r[j]);
        }
        __syncthreads();
    }

    // epilogue
    const int er = lane >> 2;
    const int ec = (lane & 3) * 2;
    #pragma unroll
    for (int i = 0; i < 4; ++i) {
        const int row = bm + wm * 64 + i * 16 + er;
        float* crow0 = C + (size_t)row * N_LAT + bn + wn * 32;
        float* crow1 = crow0 + (size_t)8 * N_LAT;
        #pragma unroll
        for (int j = 0; j < 4; ++j) {
            const int colb = j * 8 + ec;
            const float bz0 = sBias[wn * 32 + colb];
            const float bz1 = sBias[wn * 32 + colb + 1];
            float2 v0 = make_float2(acc[i][j][0] + bz0, acc[i][j][1] + bz1);
            float2 v1 = make_float2(acc[i][j][2] + bz0, acc[i][j][3] + bz1);
            *(float2*)(crow0 + colb) = v0;
            *(float2*)(crow1 + colb) = v1;
        }
    }
}

// ---------------------------------------------------------------------------
// Kernel: W_dec [D_MODEL, N_LAT] -> g_WdecT [N_LAT, D_MODEL]
// ---------------------------------------------------------------------------
__global__ void transpose_kernel(const float* __restrict__ Wdec)
{
    __shared__ float tile[32][33];
    const int l  = blockIdx.x * 32 + threadIdx.x;
    const int d0 = blockIdx.y * 32;
    #pragma unroll
    for (int j = threadIdx.y; j < 32; j += 8)
        tile[j][threadIdx.x] = Wdec[(size_t)(d0 + j) * N_LAT + l];
    __syncthreads();
    const int d  = d0 + threadIdx.x;
    const int l0 = blockIdx.x * 32;
    #pragma unroll
    for (int j = threadIdx.y; j < 32; j += 8)
        g_WdecT[(size_t)(l0 + j) * D_MODEL + d] = tile[threadIdx.x][j];
}

// ---------------------------------------------------------------------------
// Kernel: top-NCAND candidates per row, 4-pass radix select.
// Parallel suffix-scan bucket selection + multi-warp collect.
// ---------------------------------------------------------------------------
__global__ void topk_kernel(const float* __restrict__ pre)
{
    extern __shared__ unsigned skeys[];        // 16384 keys
    __shared__ unsigned hist[256];
    __shared__ unsigned suff[257];
    __shared__ unsigned s_prefix, s_remk;
    __shared__ unsigned wcnt_g[8], wcnt_e[8];

    const int row = blockIdx.x;
    const float* prow = pre + (size_t)row * N_LAT;
    const int tid = threadIdx.x;
    const int wrp = tid >> 5;
    const int lid = tid & 31;

    for (int i = tid; i < N_LAT; i += 256) {
        unsigned u = __float_as_uint(prow[i]);
        skeys[i] = (u & 0x80000000u) ? ~u : (u | 0x80000000u);
    }
    __syncthreads();

    unsigned prefix = 0u, remk = NCAND;
    for (int shift = 24; shift >= 0; shift -= 8) {
        const unsigned mask_hi = (shift == 24) ? 0u : (0xFFFFFFFFu << (shift + 8));
        hist[tid] = 0u;
        __syncthreads();
        for (int i = tid; i < N_LAT; i += 256) {
            unsigned k = skeys[i];
            if ((k & mask_hi) == prefix)
                atomicAdd(&hist[(k >> shift) & 0xFFu], 1u);
        }
        __syncthreads();
        // parallel suffix (inclusive, from high bucket down)
        suff[tid] = hist[tid];
        if (tid == 0) suff[256] = 0u;
        __syncthreads();
        #pragma unroll
        for (int st = 1; st < 256; st <<= 1) {
            unsigned add = (tid + st < 256) ? suff[tid + st] : 0u;
            __syncthreads();
            suff[tid] += add;
            __syncthreads();
        }
        // bucket b: suff[b] >= remk and suff[b+1] < remk
        if (suff[tid] >= remk && suff[tid + 1] < remk) {
            s_prefix = prefix | ((unsigned)tid << shift);
            s_remk   = remk - suff[tid + 1];
        }
        __syncthreads();
        prefix = s_prefix;
        remk   = s_remk;
        __syncthreads();
    }

    const unsigned T = prefix;

    // multi-warp collect: each warp owns a 2048-key segment
    const int seg0 = wrp * 2048;
    // phase 1: count
    unsigned ng = 0, ne = 0;
    for (int base = seg0; base < seg0 + 2048; base += 32) {
        const unsigned k = skeys[base + lid];
        const unsigned bg = __ballot_sync(0xFFFFFFFFu, k > T);
        const unsigned be = __ballot_sync(0xFFFFFFFFu, k == T);
        ng += __popc(bg);
        ne += __popc(be);
    }
    if (lid == 0) { wcnt_g[wrp] = ng; wcnt_e[wrp] = ne; }
    __syncthreads();
    unsigned gt_total = 0, gbase = 0, ebase = 0;
    #pragma unroll
    for (int w = 0; w < 8; ++w) {
        if (w < wrp) { gbase += wcnt_g[w]; ebase += wcnt_e[w]; }
        gt_total += wcnt_g[w];
    }
    // phase 2: write (gt slots first, eq slots after all gt, index order)
    const unsigned lmask = (1u << lid) - 1u;
    unsigned gofs = gbase, eofs = ebase;
    for (int base = seg0; base < seg0 + 2048; base += 32) {
        const unsigned k = skeys[base + lid];
        const bool gt = (k > T);
        const bool eq = (k == T);
        const unsigned bg = __ballot_sync(0xFFFFFFFFu, gt);
        const unsigned be = __ballot_sync(0xFFFFFFFFu, eq);
        int slot = -1;
        if (gt) {
            slot = (int)(gofs + __popc(bg & lmask));
        } else if (eq) {
            const unsigned ger = eofs + __popc(be & lmask);  // global eq rank
            if (ger < remk) slot = (int)(gt_total + ger);
        }
        if (slot >= 0 && slot < NCAND)
            g_cand[(size_t)row * NCAND + slot] = base + lid;
        gofs += __popc(bg);
        eofs += __popc(be);
    }
}

// ---------------------------------------------------------------------------
// Kernel: exact fp32 re-rank, strictly sequential k accumulation.
// ---------------------------------------------------------------------------
__global__ void __launch_bounds__(NCAND) rerank_kernel(
    const float* __restrict__ x, const float* __restrict__ W_enc,
    const float* __restrict__ b_enc, float* __restrict__ latents)
{
    __shared__ float sx[D_MODEL];
    __shared__ float sval[NCAND];
    __shared__ int   sidx[NCAND];

    const int row = blockIdx.x;
    const int tid = threadIdx.x;

    for (int i = tid; i < D_MODEL; i += NCAND)
        sx[i] = x[(size_t)row * D_MODEL + i];
    sidx[tid] = g_cand[(size_t)row * NCAND + tid];
    __syncthreads();

    const int idx = sidx[tid];
    const float* __restrict__ wrow = W_enc + (size_t)idx * D_MODEL;
    float acc = 0.0f;
    #pragma unroll 16
    for (int k = 0; k < D_MODEL; ++k)
        acc = fmaf(sx[k], __ldg(wrow + k), acc);
    sval[tid] = acc + b_enc[idx];
    __syncthreads();

    const float v = sval[tid];
    int rank = 0;
    #pragma unroll
    for (int j = 0; j < NCAND; ++j) {
        const float vj = sval[j];
        rank += (vj > v) || (vj == v && sidx[j] < idx);
    }
    if (rank < TOPK) {
        const float rv = fmaxf(v, 0.0f);
        g_tk_idx[(size_t)row * TOPK + rank] = idx;
        g_tk_val[(size_t)row * TOPK + rank] = rv;
        latents[(size_t)row * N_LAT + idx] = rv;
    }
}

// ---------------------------------------------------------------------------
// Kernel: sparse decode
// ---------------------------------------------------------------------------
__global__ void __launch_bounds__(256) decode_kernel(
    const float* __restrict__ b_dec, float* __restrict__ rec)
{
    const int row = blockIdx.x;
    __shared__ int   sidx[TOPK];
    __shared__ float sval[TOPK];
    const int tid = threadIdx.x;
    if (tid < TOPK) {
        sidx[tid] = g_tk_idx[(size_t)row * TOPK + tid];
        sval[tid] = g_tk_val[(size_t)row * TOPK + tid];
    }
    __syncthreads();
    for (int d = tid; d < D_MODEL; d += 256) {
        float acc = b_dec[d];
        #pragma unroll
        for (int j = 0; j < TOPK; ++j)
            acc = fmaf(sval[j], g_WdecT[(size_t)sidx[j] * D_MODEL + d], acc);
        rec[(size_t)row * D_MODEL + d] = acc;
    }
}

// ---------------------------------------------------------------------------
// Launch
// ---------------------------------------------------------------------------
extern "C" void kernel_launch(void* const* d_in, const int* in_sizes, int n_in,
                              void* d_out, int out_size)
{
    const float* x     = (const float*)d_in[0];
    const float* W_enc = (const float*)d_in[1];
    const float* b_enc = (const float*)d_in[2];
    const float* W_dec = (const float*)d_in[3];
    const float* b_dec = (const float*)d_in[4];

    float* out = (float*)d_out;
    const size_t LAT_ELEMS = (size_t)M_ROWS * N_LAT;
    const size_t REC_ELEMS = (size_t)M_ROWS * D_MODEL;
    float* latents = out;
    float* rec     = out + LAT_ELEMS;
    float* pre     = out + LAT_ELEMS + REC_ELEMS;

    cudaFuncSetAttribute(gemm_enc_mma, cudaFuncAttributeMaxDynamicSharedMemorySize, GEMM_SMEM);
    cudaFuncSetAttribute(topk_kernel, cudaFuncAttributeMaxDynamicSharedMemorySize, 65536);

    const int n_x = M_ROWS * D_MODEL;
    const int n_w = N_LAT * D_MODEL;
    split_x_kernel<<<(n_x + 255) / 256, 256>>>(x, n_x);          // 1
    split_w_kernel<<<(n_w + 255) / 256, 256>>>(W_enc, n_w);      // 2

    cudaMemsetAsync(latents, 0, LAT_ELEMS * sizeof(float), 0);   // 3

    transpose_kernel<<<dim3(N_LAT / 32, D_MODEL / 32), dim3(32, 8)>>>(W_dec);  // 4

    gemm_enc_mma<<<dim3(N_LAT / BN, M_ROWS / BM), 512, GEMM_SMEM>>>(b_enc, pre); // 5

    topk_kernel<<<M_ROWS, 256, 65536>>>(pre);

    rerank_kernel<<<M_ROWS, NCAND>>>(x, W_enc, b_enc, latents);

    decode_kernel<<<M_ROWS, 256>>>(b_dec, rec);
}

// round 7
// speedup vs baseline: 1.8419x; 1.1223x over previous
#include <cuda_runtime.h>
#include <cuda_fp16.h>
#include <stdint.h>

#define M_ROWS 8192
#define D_MODEL 768
#define N_LAT 16384
#define TOPK 32
#define NCAND 64

// GEMM tiling: 512 threads, 2x8 warps of 64x32 tiles, fp16 W-split (2 passes)
#define BM 128
#define BN 256
#define BK 32
#define KCHUNKS (D_MODEL / BK)       // 24
#define ROWB 80                       // padded row stride in bytes (32 fp16 = 64B -> 80)
#define ST_A  0
#define ST_B0 (128 * ROWB)            // 10240
#define ST_B1 (ST_B0 + 256 * ROWB)    // 30720
#define STAGE_B (ST_B1 + 256 * ROWB)  // 51200
#define NSTAGE 4
#define GEMM_SMEM (NSTAGE * STAGE_B)  // 204800

// ---------------------------------------------------------------------------
// Device scratch
// ---------------------------------------------------------------------------
__device__ __align__(16) __half g_xh[(size_t)M_ROWS * D_MODEL];
__device__ __align__(16) __half g_b0[(size_t)N_LAT * D_MODEL];
__device__ __align__(16) __half g_b1[(size_t)N_LAT * D_MODEL];
__device__ float g_WdecT[(size_t)N_LAT * D_MODEL];
__device__ int   g_cand[(size_t)M_ROWS * NCAND];
__device__ int   g_tk_idx[(size_t)M_ROWS * TOPK];
__device__ float g_tk_val[(size_t)M_ROWS * TOPK];

// ---------------------------------------------------------------------------
// PTX helpers (baseline sm_80+ features only)
// ---------------------------------------------------------------------------
__device__ __forceinline__ uint32_t smem_u32(const void* p) {
    uint32_t a;
    asm("{ .reg .u64 t; cvta.to.shared.u64 t, %1; cvt.u32.u64 %0, t; }"
        : "=r"(a) : "l"(p));
    return a;
}
__device__ __forceinline__ void cp16(uint32_t dst, const void* src) {
    asm volatile("cp.async.cg.shared.global [%0], [%1], 16;"
                 :: "r"(dst), "l"(src) : "memory");
}
__device__ __forceinline__ void cp_commit() {
    asm volatile("cp.async.commit_group;" ::: "memory");
}
template <int N>
__device__ __forceinline__ void cp_wait() {
    asm volatile("cp.async.wait_group %0;" :: "n"(N) : "memory");
}
__device__ __forceinline__ void ldsm4(uint32_t* r, uint32_t addr) {
    asm volatile("ldmatrix.sync.aligned.m8n8.x4.shared.b16 {%0,%1,%2,%3}, [%4];"
                 : "=r"(r[0]), "=r"(r[1]), "=r"(r[2]), "=r"(r[3]) : "r"(addr));
}
__device__ __forceinline__ void mma16816(float* c, const uint32_t* a, const uint32_t* b) {
    asm volatile(
        "mma.sync.aligned.m16n8k16.row.col.f32.f16.f16.f32 "
        "{%0,%1,%2,%3}, {%4,%5,%6,%7}, {%8,%9}, {%0,%1,%2,%3};"
        : "+f"(c[0]), "+f"(c[1]), "+f"(c[2]), "+f"(c[3])
        : "r"(a[0]), "r"(a[1]), "r"(a[2]), "r"(a[3]), "r"(b[0]), "r"(b[1]));
}

// ---------------------------------------------------------------------------
// Kernels: fp16 conversions / splits
// ---------------------------------------------------------------------------
__global__ void split_x_kernel(const float* __restrict__ src, int n)
{
    int i = blockIdx.x * blockDim.x + threadIdx.x;
    if (i < n) g_xh[i] = __float2half_rn(src[i]);
}
__global__ void split_w_kernel(const float* __restrict__ src, int n)
{
    int i = blockIdx.x * blockDim.x + threadIdx.x;
    if (i < n) {
        float v = src[i];
        __half h0 = __float2half_rn(v);
        g_b0[i] = h0;
        g_b1[i] = __float2half_rn(v - __half2float(h0));
    }
}

// ---------------------------------------------------------------------------
// Kernel: encoder GEMM, mma.sync fp16 W-split (2 passes), 512 threads,
// 64x32 warp tiles, 4-stage cp.async pipeline.
// pre[M, N_LAT] ~= fp16(x) * (b0 + b1)^T + bias
// ---------------------------------------------------------------------------
__global__ void __launch_bounds__(512, 1) gemm_enc_mma(
    const float* __restrict__ bias, float* __restrict__ C)
{
    extern __shared__ char smp[];
    const uint32_t sb = smem_u32(smp);
    __shared__ float sBias[BN];

    const int tid  = threadIdx.x;
    const int wid  = tid >> 5;
    const int lane = tid & 31;
    const int wm   = wid & 1;        // 2 warps along M (64 rows each)
    const int wn   = wid >> 1;       // 8 warps along N (32 cols each)
    const int bm   = blockIdx.y * BM;
    const int bn   = blockIdx.x * BN;

    if (tid < BN) sBias[tid] = bias[bn + tid];

    // A ldmatrix.x4 addressing: 4 m16 tiles per warp
    const int q  = lane >> 3;
    const int lr = lane & 7;
    int rbA[4];
    #pragma unroll
    for (int i = 0; i < 4; ++i)
        rbA[i] = (wm * 64 + i * 16 + (q & 1) * 8 + lr) * ROWB + (q >> 1) * 16;
    // B ldmatrix.x4 addressing: pair p covers n8 tiles 2p, 2p+1 (warp N=32 -> p<2)
    int rbB[2];
    #pragma unroll
    for (int p = 0; p < 2; ++p)
        rbB[p] = (wn * 32 + (2 * p + (lane >> 4)) * 8 + lr) * ROWB + ((lane >> 3) & 1) * 16;

    float acc[4][4][4];
    #pragma unroll
    for (int i = 0; i < 4; ++i)
        #pragma unroll
        for (int j = 0; j < 4; ++j)
            #pragma unroll
            for (int k = 0; k < 4; ++k)
                acc[i][j][k] = 0.0f;

    // cp.async: 640 rows x 4 segs = 2560 cp16 per chunk, 5 per thread
    auto cp_chunk = [&](int c, int st) {
        const int kt = c * BK;
        const uint32_t base = sb + st * STAGE_B;
        #pragma unroll
        for (int i = 0; i < 5; ++i) {
            const int u   = tid + 512 * i;
            const int seg = u & 3;
            const int r   = u >> 2;
            if (r < 128) {
                cp16(base + ST_A + r * ROWB + seg * 16,
                     g_xh + (size_t)(bm + r) * D_MODEL + kt + seg * 8);
            } else if (r < 384) {
                const int rr = r - 128;
                cp16(base + ST_B0 + rr * ROWB + seg * 16,
                     g_b0 + (size_t)(bn + rr) * D_MODEL + kt + seg * 8);
            } else {
                const int rr = r - 384;
                cp16(base + ST_B1 + rr * ROWB + seg * 16,
                     g_b1 + (size_t)(bn + rr) * D_MODEL + kt + seg * 8);
            }
        }
        cp_commit();
    };

    cp_chunk(0, 0);
    cp_chunk(1, 1);
    cp_chunk(2, 2);

    for (int c = 0; c < KCHUNKS; ++c) {
        if (c <= KCHUNKS - 3)      cp_wait<2>();
        else if (c == KCHUNKS - 2) cp_wait<1>();
        else                       cp_wait<0>();
        __syncthreads();
        if (c + 3 < KCHUNKS) cp_chunk(c + 3, (c + 3) % NSTAGE);

        const uint32_t base = sb + (c % NSTAGE) * STAGE_B;
        #pragma unroll
        for (int s = 0; s < 2; ++s) {
            const int so = s * 32;
            uint32_t af[4][4], br[4][2];
            #pragma unroll
            for (int i = 0; i < 4; ++i) ldsm4(af[i], base + ST_A + rbA[i] + so);
            // pass 1: a * b0
            #pragma unroll
            for (int p = 0; p < 2; ++p) {
                uint32_t t[4];
                ldsm4(t, base + ST_B0 + rbB[p] + so);
                br[2*p][0] = t[0]; br[2*p][1] = t[1];
                br[2*p+1][0] = t[2]; br[2*p+1][1] = t[3];
            }
            #pragma unroll
            for (int i = 0; i < 4; ++i)
                #pragma unroll
                for (int j = 0; j < 4; ++j) mma16816(acc[i][j], af[i], br[j]);
            // pass 2: a * b1
            #pragma unroll
            for (int p = 0; p < 2; ++p) {
                uint32_t t[4];
                ldsm4(t, base + ST_B1 + rbB[p] + so);
                br[2*p][0] = t[0]; br[2*p][1] = t[1];
                br[2*p+1][0] = t[2]; br[2*p+1][1] = t[3];
            }
            #pragma unroll
            for (int i = 0; i < 4; ++i)
                #pragma unroll
                for (int j = 0; j < 4; ++j) mma16816(acc[i][j], af[i], br[j]);
        }
        __syncthreads();
    }

    // epilogue
    const int er = lane >> 2;
    const int ec = (lane & 3) * 2;
    #pragma unroll
    for (int i = 0; i < 4; ++i) {
        const int row = bm + wm * 64 + i * 16 + er;
        float* crow0 = C + (size_t)row * N_LAT + bn + wn * 32;
        float* crow1 = crow0 + (size_t)8 * N_LAT;
        #pragma unroll
        for (int j = 0; j < 4; ++j) {
            const int colb = j * 8 + ec;
            const float bz0 = sBias[wn * 32 + colb];
            const float bz1 = sBias[wn * 32 + colb + 1];
            float2 v0 = make_float2(acc[i][j][0] + bz0, acc[i][j][1] + bz1);
            float2 v1 = make_float2(acc[i][j][2] + bz0, acc[i][j][3] + bz1);
            *(float2*)(crow0 + colb) = v0;
            *(float2*)(crow1 + colb) = v1;
        }
    }
}

// ---------------------------------------------------------------------------
// Kernel: W_dec [D_MODEL, N_LAT] -> g_WdecT [N_LAT, D_MODEL]
// ---------------------------------------------------------------------------
__global__ void transpose_kernel(const float* __restrict__ Wdec)
{
    __shared__ float tile[32][33];
    const int l  = blockIdx.x * 32 + threadIdx.x;
    const int d0 = blockIdx.y * 32;
    #pragma unroll
    for (int j = threadIdx.y; j < 32; j += 8)
        tile[j][threadIdx.x] = Wdec[(size_t)(d0 + j) * N_LAT + l];
    __syncthreads();
    const int d  = d0 + threadIdx.x;
    const int l0 = blockIdx.x * 32;
    #pragma unroll
    for (int j = threadIdx.y; j < 32; j += 8)
        g_WdecT[(size_t)(l0 + j) * D_MODEL + d] = tile[threadIdx.x][j];
}

// ---------------------------------------------------------------------------
// Kernel: top-NCAND candidates per row, 4-pass radix select.
// ---------------------------------------------------------------------------
__global__ void topk_kernel(const float* __restrict__ pre)
{
    extern __shared__ unsigned skeys[];        // 16384 keys
    __shared__ unsigned hist[256];
    __shared__ unsigned suff[257];
    __shared__ unsigned s_prefix, s_remk;
    __shared__ unsigned wcnt_g[8], wcnt_e[8];

    const int row = blockIdx.x;
    const float* prow = pre + (size_t)row * N_LAT;
    const int tid = threadIdx.x;
    const int wrp = tid >> 5;
    const int lid = tid & 31;

    for (int i = tid; i < N_LAT; i += 256) {
        unsigned u = __float_as_uint(prow[i]);
        skeys[i] = (u & 0x80000000u) ? ~u : (u | 0x80000000u);
    }
    __syncthreads();

    unsigned prefix = 0u, remk = NCAND;
    for (int shift = 24; shift >= 0; shift -= 8) {
        const unsigned mask_hi = (shift == 24) ? 0u : (0xFFFFFFFFu << (shift + 8));
        hist[tid] = 0u;
        __syncthreads();
        for (int i = tid; i < N_LAT; i += 256) {
            unsigned k = skeys[i];
            if ((k & mask_hi) == prefix)
                atomicAdd(&hist[(k >> shift) & 0xFFu], 1u);
        }
        __syncthreads();
        suff[tid] = hist[tid];
        if (tid == 0) suff[256] = 0u;
        __syncthreads();
        #pragma unroll
        for (int st = 1; st < 256; st <<= 1) {
            unsigned add = (tid + st < 256) ? suff[tid + st] : 0u;
            __syncthreads();
            suff[tid] += add;
            __syncthreads();
        }
        if (suff[tid] >= remk && suff[tid + 1] < remk) {
            s_prefix = prefix | ((unsigned)tid << shift);
            s_remk   = remk - suff[tid + 1];
        }
        __syncthreads();
        prefix = s_prefix;
        remk   = s_remk;
        __syncthreads();
    }

    const unsigned T = prefix;

    const int seg0 = wrp * 2048;
    unsigned ng = 0, ne = 0;
    for (int base = seg0; base < seg0 + 2048; base += 32) {
        const unsigned k = skeys[base + lid];
        ng += __popc(__ballot_sync(0xFFFFFFFFu, k > T));
        ne += __popc(__ballot_sync(0xFFFFFFFFu, k == T));
    }
    if (lid == 0) { wcnt_g[wrp] = ng; wcnt_e[wrp] = ne; }
    __syncthreads();
    unsigned gt_total = 0, gbase = 0, ebase = 0;
    #pragma unroll
    for (int w = 0; w < 8; ++w) {
        if (w < wrp) { gbase += wcnt_g[w]; ebase += wcnt_e[w]; }
        gt_total += wcnt_g[w];
    }
    const unsigned lmask = (1u << lid) - 1u;
    unsigned gofs = gbase, eofs = ebase;
    for (int base = seg0; base < seg0 + 2048; base += 32) {
        const unsigned k = skeys[base + lid];
        const bool gt = (k > T);
        const bool eq = (k == T);
        const unsigned bg = __ballot_sync(0xFFFFFFFFu, gt);
        const unsigned be = __ballot_sync(0xFFFFFFFFu, eq);
        int slot = -1;
        if (gt) {
            slot = (int)(gofs + __popc(bg & lmask));
        } else if (eq) {
            const unsigned ger = eofs + __popc(be & lmask);
            if (ger < remk) slot = (int)(gt_total + ger);
        }
        if (slot >= 0 && slot < NCAND)
            g_cand[(size_t)row * NCAND + slot] = base + lid;
        gofs += __popc(bg);
        eofs += __popc(be);
    }
}

// ---------------------------------------------------------------------------
// Kernel: exact fp32 re-rank, strictly sequential k accumulation.
// ---------------------------------------------------------------------------
__global__ void __launch_bounds__(NCAND) rerank_kernel(
    const float* __restrict__ x, const float* __restrict__ W_enc,
    const float* __restrict__ b_enc, float* __restrict__ latents)
{
    __shared__ float sx[D_MODEL];
    __shared__ float sval[NCAND];
    __shared__ int   sidx[NCAND];

    const int row = blockIdx.x;
    const int tid = threadIdx.x;

    for (int i = tid; i < D_MODEL; i += NCAND)
        sx[i] = x[(size_t)row * D_MODEL + i];
    sidx[tid] = g_cand[(size_t)row * NCAND + tid];
    __syncthreads();

    const int idx = sidx[tid];
    const float* __restrict__ wrow = W_enc + (size_t)idx * D_MODEL;
    float acc = 0.0f;
    #pragma unroll 16
    for (int k = 0; k < D_MODEL; ++k)
        acc = fmaf(sx[k], __ldg(wrow + k), acc);
    sval[tid] = acc + b_enc[idx];
    __syncthreads();

    const float v = sval[tid];
    int rank = 0;
    #pragma unroll
    for (int j = 0; j < NCAND; ++j) {
        const float vj = sval[j];
        rank += (vj > v) || (vj == v && sidx[j] < idx);
    }
    if (rank < TOPK) {
        const float rv = fmaxf(v, 0.0f);
        g_tk_idx[(size_t)row * TOPK + rank] = idx;
        g_tk_val[(size_t)row * TOPK + rank] = rv;
        latents[(size_t)row * N_LAT + idx] = rv;
    }
}

// ---------------------------------------------------------------------------
// Kernel: sparse decode
// ---------------------------------------------------------------------------
__global__ void __launch_bounds__(256) decode_kernel(
    const float* __restrict__ b_dec, float* __restrict__ rec)
{
    const int row = blockIdx.x;
    __shared__ int   sidx[TOPK];
    __shared__ float sval[TOPK];
    const int tid = threadIdx.x;
    if (tid < TOPK) {
        sidx[tid] = g_tk_idx[(size_t)row * TOPK + tid];
        sval[tid] = g_tk_val[(size_t)row * TOPK + tid];
    }
    __syncthreads();
    for (int d = tid; d < D_MODEL; d += 256) {
        float acc = b_dec[d];
        #pragma unroll
        for (int j = 0; j < TOPK; ++j)
            acc = fmaf(sval[j], g_WdecT[(size_t)sidx[j] * D_MODEL + d], acc);
        rec[(size_t)row * D_MODEL + d] = acc;
    }
}

// ---------------------------------------------------------------------------
// Launch
// ---------------------------------------------------------------------------
extern "C" void kernel_launch(void* const* d_in, const int* in_sizes, int n_in,
                              void* d_out, int out_size)
{
    const float* x     = (const float*)d_in[0];
    const float* W_enc = (const float*)d_in[1];
    const float* b_enc = (const float*)d_in[2];
    const float* W_dec = (const float*)d_in[3];
    const float* b_dec = (const float*)d_in[4];

    float* out = (float*)d_out;
    const size_t LAT_ELEMS = (size_t)M_ROWS * N_LAT;
    const size_t REC_ELEMS = (size_t)M_ROWS * D_MODEL;
    float* latents = out;
    float* rec     = out + LAT_ELEMS;
    float* pre     = out + LAT_ELEMS + REC_ELEMS;

    cudaFuncSetAttribute(gemm_enc_mma, cudaFuncAttributeMaxDynamicSharedMemorySize, GEMM_SMEM);
    cudaFuncSetAttribute(topk_kernel, cudaFuncAttributeMaxDynamicSharedMemorySize, 65536);

    const int n_x = M_ROWS * D_MODEL;
    const int n_w = N_LAT * D_MODEL;
    split_x_kernel<<<(n_x + 255) / 256, 256>>>(x, n_x);          // 1
    split_w_kernel<<<(n_w + 255) / 256, 256>>>(W_enc, n_w);      // 2

    cudaMemsetAsync(latents, 0, LAT_ELEMS * sizeof(float), 0);   // 3

    transpose_kernel<<<dim3(N_LAT / 32, D_MODEL / 32), dim3(32, 8)>>>(W_dec);  // 4

    gemm_enc_mma<<<dim3(N_LAT / BN, M_ROWS / BM), 512, GEMM_SMEM>>>(b_enc, pre); // 5

    topk_kernel<<<M_ROWS, 256, 65536>>>(pre);

    rerank_kernel<<<M_ROWS, NCAND>>>(x, W_enc, b_enc, latents);

    decode_kernel<<<M_ROWS, 256>>>(b_dec, rec);
}

// round 10
// speedup vs baseline: 1.8875x; 1.0248x over previous
#include <cuda_runtime.h>
#include <cuda_fp16.h>
#include <stdint.h>

#define M_ROWS 8192
#define D_MODEL 768
#define N_LAT 16384
#define TOPK 32
#define NCAND 64

// GEMM tiling: 256 threads/CTA (8 warps of 64x32), 2 CTAs/SM, fp16 W-split
#define BM 128
#define BN 128
#define BK 32
#define KCHUNKS (D_MODEL / BK)       // 24
#define ROWB 80                       // padded row stride in bytes
#define ST_A  0
#define ST_B0 (128 * ROWB)            // 10240
#define ST_B1 (2 * 128 * ROWB)        // 20480
#define STAGE_B (3 * 128 * ROWB)      // 30720
#define NSTAGE 3
#define GEMM_SMEM (NSTAGE * STAGE_B)  // 92160

// ---------------------------------------------------------------------------
// Device scratch
// ---------------------------------------------------------------------------
__device__ __align__(16) __half g_xh[(size_t)M_ROWS * D_MODEL];
__device__ __align__(16) __half g_b0[(size_t)N_LAT * D_MODEL];
__device__ __align__(16) __half g_b1[(size_t)N_LAT * D_MODEL];
__device__ float g_WdecT[(size_t)N_LAT * D_MODEL];
__device__ int   g_cand[(size_t)M_ROWS * NCAND];
__device__ int   g_tk_idx[(size_t)M_ROWS * TOPK];
__device__ float g_tk_val[(size_t)M_ROWS * TOPK];

// ---------------------------------------------------------------------------
// PTX helpers (baseline sm_80+ features only)
// ---------------------------------------------------------------------------
__device__ __forceinline__ uint32_t smem_u32(const void* p) {
    uint32_t a;
    asm("{ .reg .u64 t; cvta.to.shared.u64 t, %1; cvt.u32.u64 %0, t; }"
        : "=r"(a) : "l"(p));
    return a;
}
__device__ __forceinline__ void cp16(uint32_t dst, const void* src) {
    asm volatile("cp.async.cg.shared.global [%0], [%1], 16;"
                 :: "r"(dst), "l"(src) : "memory");
}
__device__ __forceinline__ void cp_commit() {
    asm volatile("cp.async.commit_group;" ::: "memory");
}
template <int N>
__device__ __forceinline__ void cp_wait() {
    asm volatile("cp.async.wait_group %0;" :: "n"(N) : "memory");
}
__device__ __forceinline__ void ldsm4(uint32_t* r, uint32_t addr) {
    asm volatile("ldmatrix.sync.aligned.m8n8.x4.shared.b16 {%0,%1,%2,%3}, [%4];"
                 : "=r"(r[0]), "=r"(r[1]), "=r"(r[2]), "=r"(r[3]) : "r"(addr));
}
__device__ __forceinline__ void mma16816(float* c, const uint32_t* a, const uint32_t* b) {
    asm volatile(
        "mma.sync.aligned.m16n8k16.row.col.f32.f16.f16.f32 "
        "{%0,%1,%2,%3}, {%4,%5,%6,%7}, {%8,%9}, {%0,%1,%2,%3};"
        : "+f"(c[0]), "+f"(c[1]), "+f"(c[2]), "+f"(c[3])
        : "r"(a[0]), "r"(a[1]), "r"(a[2]), "r"(a[3]), "r"(b[0]), "r"(b[1]));
}

// ---------------------------------------------------------------------------
// Kernels: fp16 conversions / splits
// ---------------------------------------------------------------------------
__global__ void split_x_kernel(const float* __restrict__ src, int n)
{
    int i = blockIdx.x * blockDim.x + threadIdx.x;
    if (i < n) g_xh[i] = __float2half_rn(src[i]);
}
__global__ void split_w_kernel(const float* __restrict__ src, int n)
{
    int i = blockIdx.x * blockDim.x + threadIdx.x;
    if (i < n) {
        float v = src[i];
        __half h0 = __float2half_rn(v);
        g_b0[i] = h0;
        g_b1[i] = __float2half_rn(v - __half2float(h0));
    }
}

// ---------------------------------------------------------------------------
// Kernel: encoder GEMM, mma.sync fp16 W-split (2 passes), 256 threads,
// 2 CTAs/SM (barrier decoupling), 64x32 warp tiles, 3-stage cp.async.
// ---------------------------------------------------------------------------
__global__ void __launch_bounds__(256, 2) gemm_enc_mma(
    const float* __restrict__ bias, float* __restrict__ C)
{
    extern __shared__ char smp[];
    const uint32_t sb = smem_u32(smp);
    __shared__ float sBias[BN];

    const int tid  = threadIdx.x;
    const int wid  = tid >> 5;
    const int lane = tid & 31;
    const int wm   = wid & 1;        // 2 warps along M (64 rows each)
    const int wn   = wid >> 1;       // 4 warps along N (32 cols each)
    const int bm   = blockIdx.y * BM;
    const int bn   = blockIdx.x * BN;

    if (tid < BN) sBias[tid] = bias[bn + tid];

    // A ldmatrix.x4 addressing: 4 m16 tiles per warp
    const int q  = lane >> 3;
    const int lr = lane & 7;
    int rbA[4];
    #pragma unroll
    for (int i = 0; i < 4; ++i)
        rbA[i] = (wm * 64 + i * 16 + (q & 1) * 8 + lr) * ROWB + (q >> 1) * 16;
    // B ldmatrix.x4 addressing: pair p covers n8 tiles 2p, 2p+1
    int rbB[2];
    #pragma unroll
    for (int p = 0; p < 2; ++p)
        rbB[p] = (wn * 32 + (2 * p + (lane >> 4)) * 8 + lr) * ROWB + ((lane >> 3) & 1) * 16;

    float acc[4][4][4];
    #pragma unroll
    for (int i = 0; i < 4; ++i)
        #pragma unroll
        for (int j = 0; j < 4; ++j)
            #pragma unroll
            for (int k = 0; k < 4; ++k)
                acc[i][j][k] = 0.0f;

    // cp.async: 384 rows x 4 segs = 1536 cp16 per chunk, 6 per thread
    auto cp_chunk = [&](int c, int st) {
        const int kt = c * BK;
        const uint32_t base = sb + st * STAGE_B;
        #pragma unroll
        for (int i = 0; i < 6; ++i) {
            const int u   = tid + 256 * i;
            const int seg = u & 3;
            const int r   = u >> 2;
            if (r < 128) {
                cp16(base + ST_A + r * ROWB + seg * 16,
                     g_xh + (size_t)(bm + r) * D_MODEL + kt + seg * 8);
            } else if (r < 256) {
                const int rr = r - 128;
                cp16(base + ST_B0 + rr * ROWB + seg * 16,
                     g_b0 + (size_t)(bn + rr) * D_MODEL + kt + seg * 8);
            } else {
                const int rr = r - 256;
                cp16(base + ST_B1 + rr * ROWB + seg * 16,
                     g_b1 + (size_t)(bn + rr) * D_MODEL + kt + seg * 8);
            }
        }
        cp_commit();
    };

    cp_chunk(0, 0);
    cp_chunk(1, 1);

    for (int c = 0; c < KCHUNKS; ++c) {
        if (c < KCHUNKS - 1) cp_wait<1>(); else cp_wait<0>();
        __syncthreads();
        if (c + 2 < KCHUNKS) cp_chunk(c + 2, (c + 2) % NSTAGE);

        const uint32_t base = sb + (c % NSTAGE) * STAGE_B;
        #pragma unroll
        for (int s = 0; s < 2; ++s) {
            const int so = s * 32;
            uint32_t af[4][4], br[4][2];
            #pragma unroll
            for (int i = 0; i < 4; ++i) ldsm4(af[i], base + ST_A + rbA[i] + so);
            // pass 1: a * b0
            #pragma unroll
            for (int p = 0; p < 2; ++p) {
                uint32_t t[4];
                ldsm4(t, base + ST_B0 + rbB[p] + so);
                br[2*p][0] = t[0]; br[2*p][1] = t[1];
                br[2*p+1][0] = t[2]; br[2*p+1][1] = t[3];
            }
            #pragma unroll
            for (int i = 0; i < 4; ++i)
                #pragma unroll
                for (int j = 0; j < 4; ++j) mma16816(acc[i][j], af[i], br[j]);
            // pass 2: a * b1
            #pragma unroll
            for (int p = 0; p < 2; ++p) {
                uint32_t t[4];
                ldsm4(t, base + ST_B1 + rbB[p] + so);
                br[2*p][0] = t[0]; br[2*p][1] = t[1];
                br[2*p+1][0] = t[2]; br[2*p+1][1] = t[3];
            }
            #pragma unroll
            for (int i = 0; i < 4; ++i)
                #pragma unroll
                for (int j = 0; j < 4; ++j) mma16816(acc[i][j], af[i], br[j]);
        }
        __syncthreads();
    }

    // epilogue
    const int er = lane >> 2;
    const int ec = (lane & 3) * 2;
    #pragma unroll
    for (int i = 0; i < 4; ++i) {
        const int row = bm + wm * 64 + i * 16 + er;
        float* crow0 = C + (size_t)row * N_LAT + bn + wn * 32;
        float* crow1 = crow0 + (size_t)8 * N_LAT;
        #pragma unroll
        for (int j = 0; j < 4; ++j) {
            const int colb = j * 8 + ec;
            const float bz0 = sBias[wn * 32 + colb];
            const float bz1 = sBias[wn * 32 + colb + 1];
            float2 v0 = make_float2(acc[i][j][0] + bz0, acc[i][j][1] + bz1);
            float2 v1 = make_float2(acc[i][j][2] + bz0, acc[i][j][3] + bz1);
            *(float2*)(crow0 + colb) = v0;
            *(float2*)(crow1 + colb) = v1;
        }
    }
}

// ---------------------------------------------------------------------------
// Kernel: W_dec [D_MODEL, N_LAT] -> g_WdecT [N_LAT, D_MODEL]
// ---------------------------------------------------------------------------
__global__ void transpose_kernel(const float* __restrict__ Wdec)
{
    __shared__ float tile[32][33];
    const int l  = blockIdx.x * 32 + threadIdx.x;
    const int d0 = blockIdx.y * 32;
    #pragma unroll
    for (int j = threadIdx.y; j < 32; j += 8)
        tile[j][threadIdx.x] = Wdec[(size_t)(d0 + j) * N_LAT + l];
    __syncthreads();
    const int d  = d0 + threadIdx.x;
    const int l0 = blockIdx.x * 32;
    #pragma unroll
    for (int j = threadIdx.y; j < 32; j += 8)
        g_WdecT[(size_t)(l0 + j) * D_MODEL + d] = tile[threadIdx.x][j];
}

// ---------------------------------------------------------------------------
// Kernel: top-NCAND candidates per row, 4-pass radix select.
// Ladder suffix-scan (proven in R6/R7) + multi-warp collect.
// ---------------------------------------------------------------------------
__global__ void topk_kernel(const float* __restrict__ pre)
{
    extern __shared__ unsigned skeys[];        // 16384 keys
    __shared__ unsigned hist[256];
    __shared__ unsigned suff[257];
    __shared__ unsigned s_prefix, s_remk;
    __shared__ unsigned wcnt_g[8], wcnt_e[8];

    const int row = blockIdx.x;
    const float* prow = pre + (size_t)row * N_LAT;
    const int tid = threadIdx.x;
    const int wrp = tid >> 5;
    const int lid = tid & 31;

    for (int i = tid; i < N_LAT; i += 256) {
        unsigned u = __float_as_uint(prow[i]);
        skeys[i] = (u & 0x80000000u) ? ~u : (u | 0x80000000u);
    }
    __syncthreads();

    unsigned prefix = 0u, remk = NCAND;
    for (int shift = 24; shift >= 0; shift -= 8) {
        const unsigned mask_hi = (shift == 24) ? 0u : (0xFFFFFFFFu << (shift + 8));
        hist[tid] = 0u;
        __syncthreads();
        for (int i = tid; i < N_LAT; i += 256) {
            unsigned k = skeys[i];
            if ((k & mask_hi) == prefix)
                atomicAdd(&hist[(k >> shift) & 0xFFu], 1u);
        }
        __syncthreads();
        suff[tid] = hist[tid];
        if (tid == 0) suff[256] = 0u;
        __syncthreads();
        #pragma unroll
        for (int st = 1; st < 256; st <<= 1) {
            unsigned add = (tid + st < 256) ? suff[tid + st] : 0u;
            __syncthreads();
            suff[tid] += add;
            __syncthreads();
        }
        if (suff[tid] >= remk && suff[tid + 1] < remk) {
            s_prefix = prefix | ((unsigned)tid << shift);
            s_remk   = remk - suff[tid + 1];
        }
        __syncthreads();
        prefix = s_prefix;
        remk   = s_remk;
        __syncthreads();
    }

    const unsigned T = prefix;

    const int seg0 = wrp * 2048;
    unsigned ng = 0, ne = 0;
    for (int base = seg0; base < seg0 + 2048; base += 32) {
        const unsigned k = skeys[base + lid];
        ng += __popc(__ballot_sync(0xFFFFFFFFu, k > T));
        ne += __popc(__ballot_sync(0xFFFFFFFFu, k == T));
    }
    if (lid == 0) { wcnt_g[wrp] = ng; wcnt_e[wrp] = ne; }
    __syncthreads();
    unsigned gt_total = 0, gbase = 0, ebase = 0;
    #pragma unroll
    for (int w = 0; w < 8; ++w) {
        if (w < wrp) { gbase += wcnt_g[w]; ebase += wcnt_e[w]; }
        gt_total += wcnt_g[w];
    }
    const unsigned lmask = (1u << lid) - 1u;
    unsigned gofs = gbase, eofs = ebase;
    for (int base = seg0; base < seg0 + 2048; base += 32) {
        const unsigned k = skeys[base + lid];
        const bool gt = (k > T);
        const bool eq = (k == T);
        const unsigned bg = __ballot_sync(0xFFFFFFFFu, gt);
        const unsigned be = __ballot_sync(0xFFFFFFFFu, eq);
        int slot = -1;
        if (gt) {
            slot = (int)(gofs + __popc(bg & lmask));
        } else if (eq) {
            const unsigned ger = eofs + __popc(be & lmask);
            if (ger < remk) slot = (int)(gt_total + ger);
        }
        if (slot >= 0 && slot < NCAND)
            g_cand[(size_t)row * NCAND + slot] = base + lid;
        gofs += __popc(bg);
        eofs += __popc(be);
    }
}

// ---------------------------------------------------------------------------
// Kernel: exact fp32 re-rank, strictly sequential k accumulation.
// ---------------------------------------------------------------------------
__global__ void __launch_bounds__(NCAND) rerank_kernel(
    const float* __restrict__ x, const float* __restrict__ W_enc,
    const float* __restrict__ b_enc, float* __restrict__ latents)
{
    __shared__ float sx[D_MODEL];
    __shared__ float sval[NCAND];
    __shared__ int   sidx[NCAND];

    const int row = blockIdx.x;
    const int tid = threadIdx.x;

    for (int i = tid; i < D_MODEL; i += NCAND)
        sx[i] = x[(size_t)row * D_MODEL + i];
    sidx[tid] = g_cand[(size_t)row * NCAND + tid];
    __syncthreads();

    const int idx = sidx[tid];
    const float* __restrict__ wrow = W_enc + (size_t)idx * D_MODEL;
    float acc = 0.0f;
    #pragma unroll 16
    for (int k = 0; k < D_MODEL; ++k)
        acc = fmaf(sx[k], __ldg(wrow + k), acc);
    sval[tid] = acc + b_enc[idx];
    __syncthreads();

    const float v = sval[tid];
    int rank = 0;
    #pragma unroll
    for (int j = 0; j < NCAND; ++j) {
        const float vj = sval[j];
        rank += (vj > v) || (vj == v && sidx[j] < idx);
    }
    if (rank < TOPK) {
        const float rv = fmaxf(v, 0.0f);
        g_tk_idx[(size_t)row * TOPK + rank] = idx;
        g_tk_val[(size_t)row * TOPK + rank] = rv;
        latents[(size_t)row * N_LAT + idx] = rv;
    }
}

// ---------------------------------------------------------------------------
// Kernel: sparse decode
// ---------------------------------------------------------------------------
__global__ void __launch_bounds__(256) decode_kernel(
    const float* __restrict__ b_dec, float* __restrict__ rec)
{
    const int row = blockIdx.x;
    __shared__ int   sidx[TOPK];
    __shared__ float sval[TOPK];
    const int tid = threadIdx.x;
    if (tid < TOPK) {
        sidx[tid] = g_tk_idx[(size_t)row * TOPK + tid];
        sval[tid] = g_tk_val[(size_t)row * TOPK + tid];
    }
    __syncthreads();
    for (int d = tid; d < D_MODEL; d += 256) {
        float acc = b_dec[d];
        #pragma unroll
        for (int j = 0; j < TOPK; ++j)
            acc = fmaf(sval[j], g_WdecT[(size_t)sidx[j] * D_MODEL + d], acc);
        rec[(size_t)row * D_MODEL + d] = acc;
    }
}

// ---------------------------------------------------------------------------
// Launch
// ---------------------------------------------------------------------------
extern "C" void kernel_launch(void* const* d_in, const int* in_sizes, int n_in,
                              void* d_out, int out_size)
{
    const float* x     = (const float*)d_in[0];
    const float* W_enc = (const float*)d_in[1];
    const float* b_enc = (const float*)d_in[2];
    const float* W_dec = (const float*)d_in[3];
    const float* b_dec = (const float*)d_in[4];

    float* out = (float*)d_out;
    const size_t LAT_ELEMS = (size_t)M_ROWS * N_LAT;
    const size_t REC_ELEMS = (size_t)M_ROWS * D_MODEL;
    float* latents = out;
    float* rec     = out + LAT_ELEMS;
    float* pre     = out + LAT_ELEMS + REC_ELEMS;

    cudaFuncSetAttribute(gemm_enc_mma, cudaFuncAttributeMaxDynamicSharedMemorySize, GEMM_SMEM);
    cudaFuncSetAttribute(topk_kernel, cudaFuncAttributeMaxDynamicSharedMemorySize, 65536);

    const int n_x = M_ROWS * D_MODEL;
    const int n_w = N_LAT * D_MODEL;
    split_x_kernel<<<(n_x + 255) / 256, 256>>>(x, n_x);          // 1
    split_w_kernel<<<(n_w + 255) / 256, 256>>>(W_enc, n_w);      // 2

    cudaMemsetAsync(latents, 0, LAT_ELEMS * sizeof(float), 0);   // 3

    transpose_kernel<<<dim3(N_LAT / 32, D_MODEL / 32), dim3(32, 8)>>>(W_dec);  // 4

    gemm_enc_mma<<<dim3(N_LAT / BN, M_ROWS / BM), 256, GEMM_SMEM>>>(b_enc, pre); // 5

    topk_kernel<<<M_ROWS, 256, 65536>>>(pre);

    rerank_kernel<<<M_ROWS, NCAND>>>(x, W_enc, b_enc, latents);

    decode_kernel<<<M_ROWS, 256>>>(b_dec, rec);
}

// round 11
// speedup vs baseline: 2.3055x; 1.2215x over previous
#include <cuda_runtime.h>
#include <cuda_fp16.h>
#include <stdint.h>

#define M_ROWS 8192
#define D_MODEL 768
#define N_LAT 16384
#define TOPK 32
#define NCAND 64

// GEMM tiling: 256 threads/CTA (8 warps of 64x32), 2 CTAs/SM, single-pass fp16
#define BM 128
#define BN 128
#define BK 32
#define KCHUNKS (D_MODEL / BK)       // 24
#define ROWB 80                       // padded row stride in bytes
#define ST_A  0
#define ST_B  (128 * ROWB)            // 10240
#define STAGE_B (2 * 128 * ROWB)      // 20480
#define NSTAGE 4
#define GEMM_SMEM (NSTAGE * STAGE_B)  // 81920 per CTA; 2 CTAs -> 160 KB

// ---------------------------------------------------------------------------
// Device scratch
// ---------------------------------------------------------------------------
__device__ __align__(16) __half g_xh[(size_t)M_ROWS * D_MODEL];
__device__ __align__(16) __half g_wh[(size_t)N_LAT * D_MODEL];
__device__ float g_WdecT[(size_t)N_LAT * D_MODEL];
__device__ int   g_cand[(size_t)M_ROWS * NCAND];
__device__ int   g_tk_idx[(size_t)M_ROWS * TOPK];
__device__ float g_tk_val[(size_t)M_ROWS * TOPK];

// ---------------------------------------------------------------------------
// PTX helpers (baseline sm_80+ features only)
// ---------------------------------------------------------------------------
__device__ __forceinline__ uint32_t smem_u32(const void* p) {
    uint32_t a;
    asm("{ .reg .u64 t; cvta.to.shared.u64 t, %1; cvt.u32.u64 %0, t; }"
        : "=r"(a) : "l"(p));
    return a;
}
__device__ __forceinline__ void cp16(uint32_t dst, const void* src) {
    asm volatile("cp.async.cg.shared.global [%0], [%1], 16;"
                 :: "r"(dst), "l"(src) : "memory");
}
__device__ __forceinline__ void cp_commit() {
    asm volatile("cp.async.commit_group;" ::: "memory");
}
template <int N>
__device__ __forceinline__ void cp_wait() {
    asm volatile("cp.async.wait_group %0;" :: "n"(N) : "memory");
}
__device__ __forceinline__ void ldsm4(uint32_t* r, uint32_t addr) {
    asm volatile("ldmatrix.sync.aligned.m8n8.x4.shared.b16 {%0,%1,%2,%3}, [%4];"
                 : "=r"(r[0]), "=r"(r[1]), "=r"(r[2]), "=r"(r[3]) : "r"(addr));
}
__device__ __forceinline__ void mma16816(float* c, const uint32_t* a, const uint32_t* b) {
    asm volatile(
        "mma.sync.aligned.m16n8k16.row.col.f32.f16.f16.f32 "
        "{%0,%1,%2,%3}, {%4,%5,%6,%7}, {%8,%9}, {%0,%1,%2,%3};"
        : "+f"(c[0]), "+f"(c[1]), "+f"(c[2]), "+f"(c[3])
        : "r"(a[0]), "r"(a[1]), "r"(a[2]), "r"(a[3]), "r"(b[0]), "r"(b[1]));
}

// ---------------------------------------------------------------------------
// Kernels: fp16 conversions
// ---------------------------------------------------------------------------
__global__ void conv_x_kernel(const float* __restrict__ src, int n)
{
    int i = blockIdx.x * blockDim.x + threadIdx.x;
    if (i < n) g_xh[i] = __float2half_rn(src[i]);
}
__global__ void conv_w_kernel(const float* __restrict__ src, int n)
{
    int i = blockIdx.x * blockDim.x + threadIdx.x;
    if (i < n) g_wh[i] = __float2half_rn(src[i]);
}

// ---------------------------------------------------------------------------
// Kernel: encoder GEMM, single-pass fp16 mma.sync, 256 threads, 2 CTAs/SM,
// 64x32 warp tiles, 4-stage cp.async pipeline.
// pre[M, N_LAT] ~= fp16(x) * fp16(W)^T + bias
// ---------------------------------------------------------------------------
__global__ void __launch_bounds__(256, 2) gemm_enc_mma(
    const float* __restrict__ bias, float* __restrict__ C)
{
    extern __shared__ char smp[];
    const uint32_t sb = smem_u32(smp);
    __shared__ float sBias[BN];

    const int tid  = threadIdx.x;
    const int wid  = tid >> 5;
    const int lane = tid & 31;
    const int wm   = wid & 1;        // 2 warps along M (64 rows each)
    const int wn   = wid >> 1;       // 4 warps along N (32 cols each)
    const int bm   = blockIdx.y * BM;
    const int bn   = blockIdx.x * BN;

    if (tid < BN) sBias[tid] = bias[bn + tid];

    // A ldmatrix.x4 addressing: 4 m16 tiles per warp
    const int q  = lane >> 3;
    const int lr = lane & 7;
    int rbA[4];
    #pragma unroll
    for (int i = 0; i < 4; ++i)
        rbA[i] = (wm * 64 + i * 16 + (q & 1) * 8 + lr) * ROWB + (q >> 1) * 16;
    // B ldmatrix.x4 addressing: pair p covers n8 tiles 2p, 2p+1
    int rbB[2];
    #pragma unroll
    for (int p = 0; p < 2; ++p)
        rbB[p] = (wn * 32 + (2 * p + (lane >> 4)) * 8 + lr) * ROWB + ((lane >> 3) & 1) * 16;

    float acc[4][4][4];
    #pragma unroll
    for (int i = 0; i < 4; ++i)
        #pragma unroll
        for (int j = 0; j < 4; ++j)
            #pragma unroll
            for (int k = 0; k < 4; ++k)
                acc[i][j][k] = 0.0f;

    // cp.async: 256 rows x 4 segs = 1024 cp16 per chunk, 4 per thread
    auto cp_chunk = [&](int c, int st) {
        const int kt = c * BK;
        const uint32_t base = sb + st * STAGE_B;
        #pragma unroll
        for (int i = 0; i < 4; ++i) {
            const int u   = tid + 256 * i;
            const int seg = u & 3;
            const int r   = u >> 2;
            if (r < 128) {
                cp16(base + ST_A + r * ROWB + seg * 16,
                     g_xh + (size_t)(bm + r) * D_MODEL + kt + seg * 8);
            } else {
                const int rr = r - 128;
                cp16(base + ST_B + rr * ROWB + seg * 16,
                     g_wh + (size_t)(bn + rr) * D_MODEL + kt + seg * 8);
            }
        }
        cp_commit();
    };

    cp_chunk(0, 0);
    cp_chunk(1, 1);
    cp_chunk(2, 2);

    for (int c = 0; c < KCHUNKS; ++c) {
        if (c <= KCHUNKS - 3)      cp_wait<2>();
        else if (c == KCHUNKS - 2) cp_wait<1>();
        else                       cp_wait<0>();
        __syncthreads();
        if (c + 3 < KCHUNKS) cp_chunk(c + 3, (c + 3) % NSTAGE);

        const uint32_t base = sb + (c % NSTAGE) * STAGE_B;
        #pragma unroll
        for (int s = 0; s < 2; ++s) {
            const int so = s * 32;
            uint32_t af[4][4], br[4][2];
            #pragma unroll
            for (int i = 0; i < 4; ++i) ldsm4(af[i], base + ST_A + rbA[i] + so);
            #pragma unroll
            for (int p = 0; p < 2; ++p) {
                uint32_t t[4];
                ldsm4(t, base + ST_B + rbB[p] + so);
                br[2*p][0] = t[0]; br[2*p][1] = t[1];
                br[2*p+1][0] = t[2]; br[2*p+1][1] = t[3];
            }
            #pragma unroll
            for (int i = 0; i < 4; ++i)
                #pragma unroll
                for (int j = 0; j < 4; ++j) mma16816(acc[i][j], af[i], br[j]);
        }
        __syncthreads();
    }

    // epilogue
    const int er = lane >> 2;
    const int ec = (lane & 3) * 2;
    #pragma unroll
    for (int i = 0; i < 4; ++i) {
        const int row = bm + wm * 64 + i * 16 + er;
        float* crow0 = C + (size_t)row * N_LAT + bn + wn * 32;
        float* crow1 = crow0 + (size_t)8 * N_LAT;
        #pragma unroll
        for (int j = 0; j < 4; ++j) {
            const int colb = j * 8 + ec;
            const float bz0 = sBias[wn * 32 + colb];
            const float bz1 = sBias[wn * 32 + colb + 1];
            float2 v0 = make_float2(acc[i][j][0] + bz0, acc[i][j][1] + bz1);
            float2 v1 = make_float2(acc[i][j][2] + bz0, acc[i][j][3] + bz1);
            *(float2*)(crow0 + colb) = v0;
            *(float2*)(crow1 + colb) = v1;
        }
    }
}

// ---------------------------------------------------------------------------
// Kernel: W_dec [D_MODEL, N_LAT] -> g_WdecT [N_LAT, D_MODEL]
// ---------------------------------------------------------------------------
__global__ void transpose_kernel(const float* __restrict__ Wdec)
{
    __shared__ float tile[32][33];
    const int l  = blockIdx.x * 32 + threadIdx.x;
    const int d0 = blockIdx.y * 32;
    #pragma unroll
    for (int j = threadIdx.y; j < 32; j += 8)
        tile[j][threadIdx.x] = Wdec[(size_t)(d0 + j) * N_LAT + l];
    __syncthreads();
    const int d  = d0 + threadIdx.x;
    const int l0 = blockIdx.x * 32;
    #pragma unroll
    for (int j = threadIdx.y; j < 32; j += 8)
        g_WdecT[(size_t)(l0 + j) * D_MODEL + d] = tile[threadIdx.x][j];
}

// ---------------------------------------------------------------------------
// Kernel: top-NCAND candidates per row, 2-pass radix select on top-16 bits.
// Ladder suffix-scan (proven) + multi-warp collect. Ties within the 16-bit
// threshold class are taken in index order (candidate superset — final
// selection is the exact fp32 rerank).
// ---------------------------------------------------------------------------
__global__ void topk_kernel(const float* __restrict__ pre)
{
    extern __shared__ unsigned skeys[];        // 16384 keys
    __shared__ unsigned hist[256];
    __shared__ unsigned suff[257];
    __shared__ unsigned s_prefix, s_remk;
    __shared__ unsigned wcnt_g[8], wcnt_e[8];

    const int row = blockIdx.x;
    const float* prow = pre + (size_t)row * N_LAT;
    const int tid = threadIdx.x;
    const int wrp = tid >> 5;
    const int lid = tid & 31;

    for (int i = tid; i < N_LAT; i += 256) {
        unsigned u = __float_as_uint(prow[i]);
        skeys[i] = (u & 0x80000000u) ? ~u : (u | 0x80000000u);
    }
    __syncthreads();

    unsigned prefix = 0u, remk = NCAND;
    #pragma unroll
    for (int pass = 0; pass < 2; ++pass) {
        const int shift = 24 - pass * 8;
        const unsigned mask_hi = (pass == 0) ? 0u : 0xFF000000u;
        hist[tid] = 0u;
        __syncthreads();
        for (int i = tid; i < N_LAT; i += 256) {
            unsigned k = skeys[i];
            if ((k & mask_hi) == prefix)
                atomicAdd(&hist[(k >> shift) & 0xFFu], 1u);
        }
        __syncthreads();
        suff[tid] = hist[tid];
        if (tid == 0) suff[256] = 0u;
        __syncthreads();
        #pragma unroll
        for (int st = 1; st < 256; st <<= 1) {
            unsigned add = (tid + st < 256) ? suff[tid + st] : 0u;
            __syncthreads();
            suff[tid] += add;
            __syncthreads();
        }
        if (suff[tid] >= remk && suff[tid + 1] < remk) {
            s_prefix = prefix | ((unsigned)tid << shift);
            s_remk   = remk - suff[tid + 1];
        }
        __syncthreads();
        prefix = s_prefix;
        remk   = s_remk;
        __syncthreads();
    }

    const unsigned T16 = prefix >> 16;   // 16-bit threshold class

    const int seg0 = wrp * 2048;
    unsigned ng = 0, ne = 0;
    for (int base = seg0; base < seg0 + 2048; base += 32) {
        const unsigned kp = skeys[base + lid] >> 16;
        ng += __popc(__ballot_sync(0xFFFFFFFFu, kp > T16));
        ne += __popc(__ballot_sync(0xFFFFFFFFu, kp == T16));
    }
    if (lid == 0) { wcnt_g[wrp] = ng; wcnt_e[wrp] = ne; }
    __syncthreads();
    unsigned gt_total = 0, gbase = 0, ebase = 0;
    #pragma unroll
    for (int w = 0; w < 8; ++w) {
        if (w < wrp) { gbase += wcnt_g[w]; ebase += wcnt_e[w]; }
        gt_total += wcnt_g[w];
    }
    const unsigned lmask = (1u << lid) - 1u;
    unsigned gofs = gbase, eofs = ebase;
    for (int base = seg0; base < seg0 + 2048; base += 32) {
        const unsigned kp = skeys[base + lid] >> 16;
        const bool gt = (kp > T16);
        const bool eq = (kp == T16);
        const unsigned bg = __ballot_sync(0xFFFFFFFFu, gt);
        const unsigned be = __ballot_sync(0xFFFFFFFFu, eq);
        int slot = -1;
        if (gt) {
            slot = (int)(gofs + __popc(bg & lmask));
        } else if (eq) {
            const unsigned ger = eofs + __popc(be & lmask);
            if (ger < remk) slot = (int)(gt_total + ger);
        }
        if (slot >= 0 && slot < NCAND)
            g_cand[(size_t)row * NCAND + slot] = base + lid;
        gofs += __popc(bg);
        eofs += __popc(be);
    }
}

// ---------------------------------------------------------------------------
// Kernel: exact fp32 re-rank, strictly sequential k accumulation.
// ---------------------------------------------------------------------------
__global__ void __launch_bounds__(NCAND) rerank_kernel(
    const float* __restrict__ x, const float* __restrict__ W_enc,
    const float* __restrict__ b_enc, float* __restrict__ latents)
{
    __shared__ float sx[D_MODEL];
    __shared__ float sval[NCAND];
    __shared__ int   sidx[NCAND];

    const int row = blockIdx.x;
    const int tid = threadIdx.x;

    for (int i = tid; i < D_MODEL; i += NCAND)
        sx[i] = x[(size_t)row * D_MODEL + i];
    sidx[tid] = g_cand[(size_t)row * NCAND + tid];
    __syncthreads();

    const int idx = sidx[tid];
    const float* __restrict__ wrow = W_enc + (size_t)idx * D_MODEL;
    float acc = 0.0f;
    #pragma unroll 16
    for (int k = 0; k < D_MODEL; ++k)
        acc = fmaf(sx[k], __ldg(wrow + k), acc);
    sval[tid] = acc + b_enc[idx];
    __syncthreads();

    const float v = sval[tid];
    int rank = 0;
    #pragma unroll
    for (int j = 0; j < NCAND; ++j) {
        const float vj = sval[j];
        rank += (vj > v) || (vj == v && sidx[j] < idx);
    }
    if (rank < TOPK) {
        const float rv = fmaxf(v, 0.0f);
        g_tk_idx[(size_t)row * TOPK + rank] = idx;
        g_tk_val[(size_t)row * TOPK + rank] = rv;
        latents[(size_t)row * N_LAT + idx] = rv;
    }
}

// ---------------------------------------------------------------------------
// Kernel: sparse decode
// ---------------------------------------------------------------------------
__global__ void __launch_bounds__(256) decode_kernel(
    const float* __restrict__ b_dec, float* __restrict__ rec)
{
    const int row = blockIdx.x;
    __shared__ int   sidx[TOPK];
    __shared__ float sval[TOPK];
    const int tid = threadIdx.x;
    if (tid < TOPK) {
        sidx[tid] = g_tk_idx[(size_t)row * TOPK + tid];
        sval[tid] = g_tk_val[(size_t)row * TOPK + tid];
    }
    __syncthreads();
    for (int d = tid; d < D_MODEL; d += 256) {
        float acc = b_dec[d];
        #pragma unroll
        for (int j = 0; j < TOPK; ++j)
            acc = fmaf(sval[j], g_WdecT[(size_t)sidx[j] * D_MODEL + d], acc);
        rec[(size_t)row * D_MODEL + d] = acc;
    }
}

// ---------------------------------------------------------------------------
// Launch
// ---------------------------------------------------------------------------
extern "C" void kernel_launch(void* const* d_in, const int* in_sizes, int n_in,
                              void* d_out, int out_size)
{
    const float* x     = (const float*)d_in[0];
    const float* W_enc = (const float*)d_in[1];
    const float* b_enc = (const float*)d_in[2];
    const float* W_dec = (const float*)d_in[3];
    const float* b_dec = (const float*)d_in[4];

    float* out = (float*)d_out;
    const size_t LAT_ELEMS = (size_t)M_ROWS * N_LAT;
    const size_t REC_ELEMS = (size_t)M_ROWS * D_MODEL;
    float* latents = out;
    float* rec     = out + LAT_ELEMS;
    float* pre     = out + LAT_ELEMS + REC_ELEMS;

    cudaFuncSetAttribute(gemm_enc_mma, cudaFuncAttributeMaxDynamicSharedMemorySize, GEMM_SMEM);
    cudaFuncSetAttribute(topk_kernel, cudaFuncAttributeMaxDynamicSharedMemorySize, 65536);

    const int n_x = M_ROWS * D_MODEL;
    const int n_w = N_LAT * D_MODEL;
    conv_x_kernel<<<(n_x + 255) / 256, 256>>>(x, n_x);           // 1
    conv_w_kernel<<<(n_w + 255) / 256, 256>>>(W_enc, n_w);       // 2

    cudaMemsetAsync(latents, 0, LAT_ELEMS * sizeof(float), 0);   // 3

    transpose_kernel<<<dim3(N_LAT / 32, D_MODEL / 32), dim3(32, 8)>>>(W_dec);  // 4

    gemm_enc_mma<<<dim3(N_LAT / BN, M_ROWS / BM), 256, GEMM_SMEM>>>(b_enc, pre); // 5

    topk_kernel<<<M_ROWS, 256, 65536>>>(pre);

    rerank_kernel<<<M_ROWS, NCAND>>>(x, W_enc, b_enc, latents);

    decode_kernel<<<M_ROWS, 256>>>(b_dec, rec);
}

// round 12
// speedup vs baseline: 2.3640x; 1.0254x over previous
#include <cuda_runtime.h>
#include <cuda_fp16.h>
#include <stdint.h>

#define M_ROWS 8192
#define D_MODEL 768
#define N_LAT 16384
#define TOPK 32
#define NCAND 64

// GEMM tiling: 256 threads/CTA (8 warps of 64x32), 2 CTAs/SM, single-pass fp16
#define BM 128
#define BN 128
#define BK 32
#define KCHUNKS (D_MODEL / BK)       // 24
#define ROWB 80                       // padded row stride in bytes
#define ST_A  0
#define ST_B  (128 * ROWB)            // 10240
#define STAGE_B (2 * 128 * ROWB)      // 20480
#define NSTAGE 4
#define GEMM_SMEM (NSTAGE * STAGE_B)  // 81920 per CTA; 2 CTAs -> 160 KB

#define TPK_T 512                     // topk threads

// ---------------------------------------------------------------------------
// Device scratch
// ---------------------------------------------------------------------------
__device__ __align__(16) __half g_xh[(size_t)M_ROWS * D_MODEL];
__device__ __align__(16) __half g_wh[(size_t)N_LAT * D_MODEL];
__device__ float g_WdecT[(size_t)N_LAT * D_MODEL];
__device__ int   g_cand[(size_t)M_ROWS * NCAND];
__device__ int   g_tk_idx[(size_t)M_ROWS * TOPK];
__device__ float g_tk_val[(size_t)M_ROWS * TOPK];

// ---------------------------------------------------------------------------
// PTX helpers (baseline sm_80+ features only)
// ---------------------------------------------------------------------------
__device__ __forceinline__ uint32_t smem_u32(const void* p) {
    uint32_t a;
    asm("{ .reg .u64 t; cvta.to.shared.u64 t, %1; cvt.u32.u64 %0, t; }"
        : "=r"(a) : "l"(p));
    return a;
}
__device__ __forceinline__ void cp16(uint32_t dst, const void* src) {
    asm volatile("cp.async.cg.shared.global [%0], [%1], 16;"
                 :: "r"(dst), "l"(src) : "memory");
}
__device__ __forceinline__ void cp_commit() {
    asm volatile("cp.async.commit_group;" ::: "memory");
}
template <int N>
__device__ __forceinline__ void cp_wait() {
    asm volatile("cp.async.wait_group %0;" :: "n"(N) : "memory");
}
__device__ __forceinline__ void ldsm4(uint32_t* r, uint32_t addr) {
    asm volatile("ldmatrix.sync.aligned.m8n8.x4.shared.b16 {%0,%1,%2,%3}, [%4];"
                 : "=r"(r[0]), "=r"(r[1]), "=r"(r[2]), "=r"(r[3]) : "r"(addr));
}
__device__ __forceinline__ void mma16816(float* c, const uint32_t* a, const uint32_t* b) {
    asm volatile(
        "mma.sync.aligned.m16n8k16.row.col.f32.f16.f16.f32 "
        "{%0,%1,%2,%3}, {%4,%5,%6,%7}, {%8,%9}, {%0,%1,%2,%3};"
        : "+f"(c[0]), "+f"(c[1]), "+f"(c[2]), "+f"(c[3])
        : "r"(a[0]), "r"(a[1]), "r"(a[2]), "r"(a[3]), "r"(b[0]), "r"(b[1]));
}
__device__ __forceinline__ unsigned short key16(float v) {
    unsigned u = __float_as_uint(v);
    unsigned m = (u & 0x80000000u) ? ~u : (u | 0x80000000u);
    return (unsigned short)(m >> 16);
}

// ---------------------------------------------------------------------------
// Kernels: fp16 conversions
// ---------------------------------------------------------------------------
__global__ void conv_x_kernel(const float* __restrict__ src, int n)
{
    int i = blockIdx.x * blockDim.x + threadIdx.x;
    if (i < n) g_xh[i] = __float2half_rn(src[i]);
}
__global__ void conv_w_kernel(const float* __restrict__ src, int n)
{
    int i = blockIdx.x * blockDim.x + threadIdx.x;
    if (i < n) g_wh[i] = __float2half_rn(src[i]);
}

// ---------------------------------------------------------------------------
// Kernel: encoder GEMM, single-pass fp16 mma.sync (unchanged from R11).
// ---------------------------------------------------------------------------
__global__ void __launch_bounds__(256, 2) gemm_enc_mma(
    const float* __restrict__ bias, float* __restrict__ C)
{
    extern __shared__ char smp[];
    const uint32_t sb = smem_u32(smp);
    __shared__ float sBias[BN];

    const int tid  = threadIdx.x;
    const int wid  = tid >> 5;
    const int lane = tid & 31;
    const int wm   = wid & 1;
    const int wn   = wid >> 1;
    const int bm   = blockIdx.y * BM;
    const int bn   = blockIdx.x * BN;

    if (tid < BN) sBias[tid] = bias[bn + tid];

    const int q  = lane >> 3;
    const int lr = lane & 7;
    int rbA[4];
    #pragma unroll
    for (int i = 0; i < 4; ++i)
        rbA[i] = (wm * 64 + i * 16 + (q & 1) * 8 + lr) * ROWB + (q >> 1) * 16;
    int rbB[2];
    #pragma unroll
    for (int p = 0; p < 2; ++p)
        rbB[p] = (wn * 32 + (2 * p + (lane >> 4)) * 8 + lr) * ROWB + ((lane >> 3) & 1) * 16;

    float acc[4][4][4];
    #pragma unroll
    for (int i = 0; i < 4; ++i)
        #pragma unroll
        for (int j = 0; j < 4; ++j)
            #pragma unroll
            for (int k = 0; k < 4; ++k)
                acc[i][j][k] = 0.0f;

    auto cp_chunk = [&](int c, int st) {
        const int kt = c * BK;
        const uint32_t base = sb + st * STAGE_B;
        #pragma unroll
        for (int i = 0; i < 4; ++i) {
            const int u   = tid + 256 * i;
            const int seg = u & 3;
            const int r   = u >> 2;
            if (r < 128) {
                cp16(base + ST_A + r * ROWB + seg * 16,
                     g_xh + (size_t)(bm + r) * D_MODEL + kt + seg * 8);
            } else {
                const int rr = r - 128;
                cp16(base + ST_B + rr * ROWB + seg * 16,
                     g_wh + (size_t)(bn + rr) * D_MODEL + kt + seg * 8);
            }
        }
        cp_commit();
    };

    cp_chunk(0, 0);
    cp_chunk(1, 1);
    cp_chunk(2, 2);

    for (int c = 0; c < KCHUNKS; ++c) {
        if (c <= KCHUNKS - 3)      cp_wait<2>();
        else if (c == KCHUNKS - 2) cp_wait<1>();
        else                       cp_wait<0>();
        __syncthreads();
        if (c + 3 < KCHUNKS) cp_chunk(c + 3, (c + 3) % NSTAGE);

        const uint32_t base = sb + (c % NSTAGE) * STAGE_B;
        #pragma unroll
        for (int s = 0; s < 2; ++s) {
            const int so = s * 32;
            uint32_t af[4][4], br[4][2];
            #pragma unroll
            for (int i = 0; i < 4; ++i) ldsm4(af[i], base + ST_A + rbA[i] + so);
            #pragma unroll
            for (int p = 0; p < 2; ++p) {
                uint32_t t[4];
                ldsm4(t, base + ST_B + rbB[p] + so);
                br[2*p][0] = t[0]; br[2*p][1] = t[1];
                br[2*p+1][0] = t[2]; br[2*p+1][1] = t[3];
            }
            #pragma unroll
            for (int i = 0; i < 4; ++i)
                #pragma unroll
                for (int j = 0; j < 4; ++j) mma16816(acc[i][j], af[i], br[j]);
        }
        __syncthreads();
    }

    const int er = lane >> 2;
    const int ec = (lane & 3) * 2;
    #pragma unroll
    for (int i = 0; i < 4; ++i) {
        const int row = bm + wm * 64 + i * 16 + er;
        float* crow0 = C + (size_t)row * N_LAT + bn + wn * 32;
        float* crow1 = crow0 + (size_t)8 * N_LAT;
        #pragma unroll
        for (int j = 0; j < 4; ++j) {
            const int colb = j * 8 + ec;
            const float bz0 = sBias[wn * 32 + colb];
            const float bz1 = sBias[wn * 32 + colb + 1];
            float2 v0 = make_float2(acc[i][j][0] + bz0, acc[i][j][1] + bz1);
            float2 v1 = make_float2(acc[i][j][2] + bz0, acc[i][j][3] + bz1);
            *(float2*)(crow0 + colb) = v0;
            *(float2*)(crow1 + colb) = v1;
        }
    }
}

// ---------------------------------------------------------------------------
// Kernel: W_dec [D_MODEL, N_LAT] -> g_WdecT [N_LAT, D_MODEL]
// ---------------------------------------------------------------------------
__global__ void transpose_kernel(const float* __restrict__ Wdec)
{
    __shared__ float tile[32][33];
    const int l  = blockIdx.x * 32 + threadIdx.x;
    const int d0 = blockIdx.y * 32;
    #pragma unroll
    for (int j = threadIdx.y; j < 32; j += 8)
        tile[j][threadIdx.x] = Wdec[(size_t)(d0 + j) * N_LAT + l];
    __syncthreads();
    const int d  = d0 + threadIdx.x;
    const int l0 = blockIdx.x * 32;
    #pragma unroll
    for (int j = threadIdx.y; j < 32; j += 8)
        g_WdecT[(size_t)(l0 + j) * D_MODEL + d] = tile[threadIdx.x][j];
}

// ---------------------------------------------------------------------------
// Kernel: top-NCAND candidates per row, 2-pass radix on 16-bit keys.
// 512 threads, 16-bit smem keys (32KB), match_any-aggregated atomics,
// fused latents-row zeroing (replaces the 512MB memset).
// ---------------------------------------------------------------------------
__global__ void __launch_bounds__(TPK_T) topk_kernel(
    const float* __restrict__ pre, float* __restrict__ latents)
{
    __shared__ __align__(16) unsigned short skey[N_LAT];   // 32 KB
    __shared__ unsigned hist[256];
    __shared__ unsigned suff[257];
    __shared__ unsigned s_b, s_remk;
    __shared__ unsigned wcnt_g[16], wcnt_e[16];

    const int row = blockIdx.x;
    const int tid = threadIdx.x;
    const int wrp = tid >> 5;
    const int lid = tid & 31;

    const float4* prow4 = (const float4*)(pre + (size_t)row * N_LAT);
    float4*       lat4  = (float4*)(latents + (size_t)row * N_LAT);

    if (tid < 256) hist[tid] = 0u;

    // load pre row, build 16-bit keys, zero the latents row
    const float4 z4 = make_float4(0.f, 0.f, 0.f, 0.f);
    #pragma unroll
    for (int j = 0; j < 8; ++j) {
        const int i4 = tid + TPK_T * j;
        float4 v = prow4[i4];
        lat4[i4] = z4;
        ushort4 kk;
        kk.x = key16(v.x); kk.y = key16(v.y);
        kk.z = key16(v.z); kk.w = key16(v.w);
        ((ushort4*)skey)[i4] = kk;
    }
    __syncthreads();

    // ---- pass 0: histogram on key bits 15..8 (aggregated atomics) ----
    #pragma unroll 4
    for (int j = 0; j < 32; ++j) {
        const unsigned b = (unsigned)(skey[tid + TPK_T * j]) >> 8;
        const unsigned peers = __match_any_sync(0xFFFFFFFFu, b);
        if ((peers & ((1u << lid) - 1u)) == 0u)
            atomicAdd(&hist[b], __popc(peers));
    }
    __syncthreads();

    // suffix scan + bucket select (256 lanes of work, all threads at barriers)
    unsigned remk = NCAND;
    if (tid < 256) suff[tid] = hist[tid];
    if (tid == 0) suff[256] = 0u;
    __syncthreads();
    #pragma unroll
    for (int st = 1; st < 256; st <<= 1) {
        unsigned add = (tid < 256 && tid + st < 256) ? suff[tid + st] : 0u;
        __syncthreads();
        if (tid < 256) suff[tid] += add;
        __syncthreads();
    }
    if (tid < 256 && suff[tid] >= remk && suff[tid + 1] < remk) {
        s_b = (unsigned)tid;
        s_remk = remk - suff[tid + 1];
    }
    __syncthreads();
    const unsigned p8 = s_b;
    remk = s_remk;
    __syncthreads();

    // ---- pass 1: histogram on key bits 7..0 within class p8 ----
    if (tid < 256) hist[tid] = 0u;
    __syncthreads();
    for (int j = 0; j < 32; ++j) {
        const unsigned k = (unsigned)skey[tid + TPK_T * j];
        const bool act = ((k >> 8) == p8);
        const unsigned amask = __ballot_sync(0xFFFFFFFFu, act);
        if (act) {
            const unsigned b = k & 0xFFu;
            const unsigned peers = __match_any_sync(amask, b);
            if ((peers & ((1u << lid) - 1u)) == 0u)
                atomicAdd(&hist[b], __popc(peers));
        }
    }
    __syncthreads();
    if (tid < 256) suff[tid] = hist[tid];
    if (tid == 0) suff[256] = 0u;
    __syncthreads();
    #pragma unroll
    for (int st = 1; st < 256; st <<= 1) {
        unsigned add = (tid < 256 && tid + st < 256) ? suff[tid + st] : 0u;
        __syncthreads();
        if (tid < 256) suff[tid] += add;
        __syncthreads();
    }
    if (tid < 256 && suff[tid] >= remk && suff[tid + 1] < remk) {
        s_b = (unsigned)tid;
        s_remk = remk - suff[tid + 1];
    }
    __syncthreads();
    const unsigned T16 = (p8 << 8) | s_b;
    remk = s_remk;
    __syncthreads();

    // ---- collect: 16 warps x 1024-key segments ----
    const int seg0 = wrp * 1024;
    unsigned ng = 0, ne = 0;
    for (int base = seg0; base < seg0 + 1024; base += 32) {
        const unsigned k = (unsigned)skey[base + lid];
        ng += __popc(__ballot_sync(0xFFFFFFFFu, k > T16));
        ne += __popc(__ballot_sync(0xFFFFFFFFu, k == T16));
    }
    if (lid == 0) { wcnt_g[wrp] = ng; wcnt_e[wrp] = ne; }
    __syncthreads();
    unsigned gt_total = 0, gbase = 0, ebase = 0;
    #pragma unroll
    for (int w = 0; w < 16; ++w) {
        if (w < wrp) { gbase += wcnt_g[w]; ebase += wcnt_e[w]; }
        gt_total += wcnt_g[w];
    }
    const unsigned lmask = (1u << lid) - 1u;
    unsigned gofs = gbase, eofs = ebase;
    for (int base = seg0; base < seg0 + 1024; base += 32) {
        const unsigned k = (unsigned)skey[base + lid];
        const bool gt = (k > T16);
        const bool eq = (k == T16);
        const unsigned bg = __ballot_sync(0xFFFFFFFFu, gt);
        const unsigned be = __ballot_sync(0xFFFFFFFFu, eq);
        int slot = -1;
        if (gt) {
            slot = (int)(gofs + __popc(bg & lmask));
        } else if (eq) {
            const unsigned ger = eofs + __popc(be & lmask);
            if (ger < remk) slot = (int)(gt_total + ger);
        }
        if (slot >= 0 && slot < NCAND)
            g_cand[(size_t)row * NCAND + slot] = base + lid;
        gofs += __popc(bg);
        eofs += __popc(be);
    }
}

// ---------------------------------------------------------------------------
// Kernel: exact fp32 re-rank, strictly sequential k accumulation.
// ---------------------------------------------------------------------------
__global__ void __launch_bounds__(NCAND) rerank_kernel(
    const float* __restrict__ x, const float* __restrict__ W_enc,
    const float* __restrict__ b_enc, float* __restrict__ latents)
{
    __shared__ float sx[D_MODEL];
    __shared__ float sval[NCAND];
    __shared__ int   sidx[NCAND];

    const int row = blockIdx.x;
    const int tid = threadIdx.x;

    for (int i = tid; i < D_MODEL; i += NCAND)
        sx[i] = x[(size_t)row * D_MODEL + i];
    sidx[tid] = g_cand[(size_t)row * NCAND + tid];
    __syncthreads();

    const int idx = sidx[tid];
    const float* __restrict__ wrow = W_enc + (size_t)idx * D_MODEL;
    float acc = 0.0f;
    #pragma unroll 16
    for (int k = 0; k < D_MODEL; ++k)
        acc = fmaf(sx[k], __ldg(wrow + k), acc);
    sval[tid] = acc + b_enc[idx];
    __syncthreads();

    const float v = sval[tid];
    int rank = 0;
    #pragma unroll
    for (int j = 0; j < NCAND; ++j) {
        const float vj = sval[j];
        rank += (vj > v) || (vj == v && sidx[j] < idx);
    }
    if (rank < TOPK) {
        const float rv = fmaxf(v, 0.0f);
        g_tk_idx[(size_t)row * TOPK + rank] = idx;
        g_tk_val[(size_t)row * TOPK + rank] = rv;
        latents[(size_t)row * N_LAT + idx] = rv;
    }
}

// ---------------------------------------------------------------------------
// Kernel: sparse decode
// ---------------------------------------------------------------------------
__global__ void __launch_bounds__(256) decode_kernel(
    const float* __restrict__ b_dec, float* __restrict__ rec)
{
    const int row = blockIdx.x;
    __shared__ int   sidx[TOPK];
    __shared__ float sval[TOPK];
    const int tid = threadIdx.x;
    if (tid < TOPK) {
        sidx[tid] = g_tk_idx[(size_t)row * TOPK + tid];
        sval[tid] = g_tk_val[(size_t)row * TOPK + tid];
    }
    __syncthreads();
    for (int d = tid; d < D_MODEL; d += 256) {
        float acc = b_dec[d];
        #pragma unroll
        for (int j = 0; j < TOPK; ++j)
            acc = fmaf(sval[j], g_WdecT[(size_t)sidx[j] * D_MODEL + d], acc);
        rec[(size_t)row * D_MODEL + d] = acc;
    }
}

// ---------------------------------------------------------------------------
// Launch
// ---------------------------------------------------------------------------
extern "C" void kernel_launch(void* const* d_in, const int* in_sizes, int n_in,
                              void* d_out, int out_size)
{
    const float* x     = (const float*)d_in[0];
    const float* W_enc = (const float*)d_in[1];
    const float* b_enc = (const float*)d_in[2];
    const float* W_dec = (const float*)d_in[3];
    const float* b_dec = (const float*)d_in[4];

    float* out = (float*)d_out;
    const size_t LAT_ELEMS = (size_t)M_ROWS * N_LAT;
    const size_t REC_ELEMS = (size_t)M_ROWS * D_MODEL;
    float* latents = out;
    float* rec     = out + LAT_ELEMS;
    float* pre     = out + LAT_ELEMS + REC_ELEMS;

    cudaFuncSetAttribute(gemm_enc_mma, cudaFuncAttributeMaxDynamicSharedMemorySize, GEMM_SMEM);

    const int n_x = M_ROWS * D_MODEL;
    const int n_w = N_LAT * D_MODEL;
    conv_x_kernel<<<(n_x + 255) / 256, 256>>>(x, n_x);           // 1
    conv_w_kernel<<<(n_w + 255) / 256, 256>>>(W_enc, n_w);       // 2

    transpose_kernel<<<dim3(N_LAT / 32, D_MODEL / 32), dim3(32, 8)>>>(W_dec);  // 3

    gemm_enc_mma<<<dim3(N_LAT / BN, M_ROWS / BM), 256, GEMM_SMEM>>>(b_enc, pre); // 4

    topk_kernel<<<M_ROWS, TPK_T>>>(pre, latents);                // 5 (zeroes latents too)

    rerank_kernel<<<M_ROWS, NCAND>>>(x, W_enc, b_enc, latents);  // 6

    decode_kernel<<<M_ROWS, 256>>>(b_dec, rec);                  // 7
}